// round 12
// baseline (speedup 1.0000x reference)
#include <cuda_runtime.h>
#include <cuda_bf16.h>
#include <cuda_fp16.h>
#include <cstdint>
#include <math.h>

// Problem constants (B=8, H=W=128, C=384, window=8)
#define TOKENS   131072              // 8*128*128
#define CDIM     384
#define NQKV     1152
#define NWIN     2048                // 8 * 16 * 16 windows

// ---------------------------------------------------------------------------
// Scratch (allocation-free rule: __device__ globals)
// g_qkv2 per-token layout (bf16): [q hi 384][q lo 384][k hi][k lo][v hi][v lo]
// ---------------------------------------------------------------------------
__device__ __nv_bfloat16 g_qkv2[(size_t)TOKENS * 2304];  // 604 MB
__device__ __half g_att_h[(size_t)TOKENS * CDIM];        // fp16 attention out (100 MB)
__device__ __half g_xh [(size_t)TOKENS * CDIM];          // fp16 x (100 MB)
__device__ __half g_Wt1[(size_t)NQKV * CDIM];            // w_qkv^T  fp16 [N][K]
__device__ __half g_Wt3[(size_t)CDIM * CDIM];            // w_proj^T fp16 [N][K]

__device__ __forceinline__ uint32_t smem_u32(const void* p) {
    uint32_t a;
    asm("{ .reg .u64 tmp; cvta.to.shared.u64 tmp, %1; cvt.u32.u64 %0, tmp; }"
        : "=r"(a) : "l"(p));
    return a;
}

// Split a float2 into packed bf16x2 hi and lo (residual) parts.
__device__ __forceinline__ void split2(float x, float y, uint32_t& hi, uint32_t& lo) {
    uint32_t h;
    asm("cvt.rn.bf16x2.f32 %0, %1, %2;" : "=r"(h) : "f"(y), "f"(x));
    float h0 = __uint_as_float(h << 16);
    float h1 = __uint_as_float(h & 0xffff0000u);
    float r0 = x - h0, r1 = y - h1;
    asm("cvt.rn.bf16x2.f32 %0, %1, %2;" : "=r"(lo) : "f"(r1), "f"(r0));
    hi = h;
}

// bf16 HMMA (attention — validated)
__device__ __forceinline__ void mma16816(float* c, const uint32_t* a,
                                         uint32_t b0, uint32_t b1) {
    asm volatile(
        "mma.sync.aligned.m16n8k16.row.col.f32.bf16.bf16.f32 "
        "{%0,%1,%2,%3}, {%4,%5,%6,%7}, {%8,%9}, {%0,%1,%2,%3};\n"
        : "+f"(c[0]), "+f"(c[1]), "+f"(c[2]), "+f"(c[3])
        : "r"(a[0]), "r"(a[1]), "r"(a[2]), "r"(a[3]), "r"(b0), "r"(b1));
}

// fp16 HMMA (GEMMs)
__device__ __forceinline__ void mma16816h(float* c, const uint32_t* a,
                                          uint32_t b0, uint32_t b1) {
    asm volatile(
        "mma.sync.aligned.m16n8k16.row.col.f32.f16.f16.f32 "
        "{%0,%1,%2,%3}, {%4,%5,%6,%7}, {%8,%9}, {%0,%1,%2,%3};\n"
        : "+f"(c[0]), "+f"(c[1]), "+f"(c[2]), "+f"(c[3])
        : "r"(a[0]), "r"(a[1]), "r"(a[2]), "r"(a[3]), "r"(b0), "r"(b1));
}

#define LDSM_X4(r, a) \
    asm volatile("ldmatrix.sync.aligned.m8n8.x4.shared.b16 {%0,%1,%2,%3}, [%4];" \
        : "=r"((r)[0]), "=r"((r)[1]), "=r"((r)[2]), "=r"((r)[3]) : "r"(a))

#define LDSM_X4_T(r, a) \
    asm volatile("ldmatrix.sync.aligned.m8n8.x4.trans.shared.b16 {%0,%1,%2,%3}, [%4];" \
        : "=r"((r)[0]), "=r"((r)[1]), "=r"((r)[2]), "=r"((r)[3]) : "r"(a))

// ---------------------------------------------------------------------------
// Weight transpose -> fp16: w [384 x N] fp32 -> out [N x 384] fp16
// ---------------------------------------------------------------------------
__global__ __launch_bounds__(256) void trans_w_kernel(
    const float* __restrict__ w, __half* __restrict__ out, int N)
{
    const int t = blockIdx.x * 256 + threadIdx.x;
    if (t >= N * CDIM) return;
    const int n = t / CDIM;
    const int k = t % CDIM;
    out[(size_t)n * CDIM + k] = __float2half(w[(size_t)k * N + n]);
}

// ---------------------------------------------------------------------------
// fp32 -> fp16 bulk convert (x)
// ---------------------------------------------------------------------------
__global__ __launch_bounds__(256) void cvt_h_kernel(
    const float* __restrict__ in, __half* __restrict__ out)
{
    const size_t t = (size_t)blockIdx.x * 256 + threadIdx.x;   // < TOKENS*96
    float4 v = *(const float4*)(in + t * 4);
    __half2 a = __floats2half2_rn(v.x, v.y);
    __half2 b = __floats2half2_rn(v.z, v.w);
    *(uint2*)(out + t * 4) = make_uint2(
        *(uint32_t*)&a, *(uint32_t*)&b);
}

// ---------------------------------------------------------------------------
// fp16 GEMM v2: 32x32 warp tile, 3 CTAs/SM (occupancy experiment).
//   BM=128, BN=64, BK=64 halfs, 256 threads (8 warps: 4M x 2N), <=85 regs.
//   Stage = A(128x128B) + B(64x128B) = 24576 B; 2 stages = 49152 B.
//   Swizzle: 16B chunk ch of row r stored at ch ^ (r & 7).
//   If Csplit != 0: epilogue writes split-bf16 planes (g_qkv2 layout).
// ---------------------------------------------------------------------------
#define STAGE_BYTES 24576u
__global__ __launch_bounds__(256, 3) void gemm_h(
    const __half* __restrict__ A,
    const __half* __restrict__ Bt,
    const float* __restrict__ bias,
    float* __restrict__ C,
    __nv_bfloat16* __restrict__ Csplit,
    int Ndim)
{
    extern __shared__ __align__(16) char smem[];
    const uint32_t smemBase = smem_u32(smem);

    const int tid  = threadIdx.x;
    const int wid  = tid >> 5;
    const int lane = tid & 31;
    const int g    = lane >> 2;
    const int t4   = lane & 3;
    const int m0   = blockIdx.y * 128;
    const int n0   = blockIdx.x * 64;
    const int wm   = (wid & 3) * 32;   // warp M offset (4 warps)
    const int wn   = (wid >> 2) * 32;  // warp N offset (2 warps)

    // cp.async: 1536 chunks of 16B per stage (A 1024 + B 512); 6 per thread
    const __half* srcs[6];
    uint32_t dsts[6];
#pragma unroll
    for (int i = 0; i < 6; i++) {
        const int id = tid + i * 256;          // < 1536
        if (id < 1024) {                       // A: 128 rows x 8 chunks
            const int r  = id >> 3;
            const int ch = id & 7;
            srcs[i] = A + (size_t)(m0 + r) * CDIM + ch * 8;
            dsts[i] = smemBase + (uint32_t)(r * 128 + ((ch ^ (r & 7)) * 16));
        } else {                               // B: 64 rows x 8 chunks
            const int id2 = id - 1024;
            const int r  = id2 >> 3;
            const int ch = id2 & 7;
            srcs[i] = Bt + (size_t)(n0 + r) * CDIM + ch * 8;
            dsts[i] = smemBase + (uint32_t)(16384 + r * 128 + ((ch ^ (r & 7)) * 16));
        }
    }

#define PREFETCH(s, off) do {                                                 \
        _Pragma("unroll")                                                     \
        for (int _i = 0; _i < 6; _i++) {                                      \
            asm volatile("cp.async.cg.shared.global [%0], [%1], 16;"          \
                :: "r"(dsts[_i] + (off)), "l"(srcs[_i] + (s) * 64));          \
        }                                                                     \
        asm volatile("cp.async.commit_group;" ::: "memory");                  \
    } while (0)

    // ldmatrix: lane row la, k16-step q -> chunk 2q + (lane>>4), swizzled
    const int la = lane & 15;
    const int h  = lane >> 4;
    const int s7 = la & 7;
    uint32_t coff[4];
#pragma unroll
    for (int q = 0; q < 4; q++)
        coff[q] = (uint32_t)((((2 * q + h) ^ s7) & 7) * 16);
    const uint32_t aBase = smemBase + (uint32_t)((wm + la) * 128);
    const uint32_t bBase = smemBase + 16384 + (uint32_t)((wn + la) * 128);

    float acc[2][4][4];
#pragma unroll
    for (int mt = 0; mt < 2; mt++)
#pragma unroll
        for (int nt = 0; nt < 4; nt++)
#pragma unroll
            for (int i = 0; i < 4; i++) acc[mt][nt][i] = 0.f;

    PREFETCH(0, 0);

#pragma unroll
    for (int s = 0; s < 6; s++) {
        asm volatile("cp.async.wait_group 0;" ::: "memory");
        __syncthreads();
        if (s < 5) PREFETCH(s + 1, ((s + 1) & 1) * STAGE_BYTES);
        const uint32_t off = (s & 1) * STAGE_BYTES;

#pragma unroll
        for (int q = 0; q < 4; q++) {              // 4 x k16 per stage
            uint32_t a[2][4];
            LDSM_X4(a[0], aBase + off + coff[q]);
            LDSM_X4(a[1], aBase + off + 2048 + coff[q]);
            uint32_t b0[4], b1[4];
            LDSM_X4(b0, bBase + off + coff[q]);
            LDSM_X4(b1, bBase + off + 2048 + coff[q]);
            mma16816h(acc[0][0], a[0], b0[0], b0[2]);
            mma16816h(acc[0][1], a[0], b0[1], b0[3]);
            mma16816h(acc[0][2], a[0], b1[0], b1[2]);
            mma16816h(acc[0][3], a[0], b1[1], b1[3]);
            mma16816h(acc[1][0], a[1], b0[0], b0[2]);
            mma16816h(acc[1][1], a[1], b0[1], b0[3]);
            mma16816h(acc[1][2], a[1], b1[0], b1[2]);
            mma16816h(acc[1][3], a[1], b1[1], b1[3]);
        }
    }
#undef PREFETCH

#pragma unroll
    for (int mt = 0; mt < 2; mt++) {
        const int r0 = m0 + wm + mt * 16 + g;
#pragma unroll
        for (int nt = 0; nt < 4; nt++) {
            const int col = n0 + wn + (nt >> 1) * 16 + (nt & 1) * 8 + t4 * 2;
            float2 bv = *(const float2*)(bias + col);
            float2 v0 = make_float2(acc[mt][nt][0] + bv.x, acc[mt][nt][1] + bv.y);
            float2 v1 = make_float2(acc[mt][nt][2] + bv.x, acc[mt][nt][3] + bv.y);
            if (Csplit) {
                const int pl = col / 384;
                const int wi = col - pl * 384;
                uint32_t hh, ll;
                __nv_bfloat16* b0 = Csplit + (size_t)r0 * 2304 + pl * 768 + wi;
                split2(v0.x, v0.y, hh, ll);
                *(uint32_t*)(b0)       = hh;
                *(uint32_t*)(b0 + 384) = ll;
                __nv_bfloat16* b1 = Csplit + (size_t)(r0 + 8) * 2304 + pl * 768 + wi;
                split2(v1.x, v1.y, hh, ll);
                *(uint32_t*)(b1)       = hh;
                *(uint32_t*)(b1 + 384) = ll;
            } else {
                *(float2*)(C + (size_t)r0 * Ndim + col) = v0;
                *(float2*)(C + (size_t)(r0 + 8) * Ndim + col) = v1;
            }
        }
    }
}

// ---------------------------------------------------------------------------
// Window attention (r10/r11, validated; fp16 output stores)
// ---------------------------------------------------------------------------
#define ATTN_SMEM 82432
__global__ __launch_bounds__(128) void window_attn()
{
    extern __shared__ __align__(16) char asm_[];
    const uint32_t sb = smem_u32(asm_);
    int* tok = (int*)(asm_ + 81920);
    float (*Ss)[65] = (float(*)[65])asm_;

    const int gb = blockIdx.x;
    const int b = gb >> 8, win = gb & 255, wy = win >> 4, wx = win & 15;
    const int tid = threadIdx.x;
    if (tid < 64) {
        int py = tid >> 3, px = tid & 7;
        tok[tid] = b * 16384 + (wy * 8 + py) * 128 + (wx * 8 + px);
    }
    __syncthreads();

    const int wid = tid >> 5, lane = tid & 31;
    const int g = lane >> 2, t4 = lane & 3;
    const int la = lane & 15, lh = lane >> 4;

    uint32_t coff[4];
#pragma unroll
    for (int q = 0; q < 4; q++)
        coff[q] = (uint32_t)((((2 * q + lh) ^ (lane & 7)) & 7) * 16);

    const __nv_bfloat16* sQK[16];
    uint32_t dQK[16];
#pragma unroll
    for (int i = 0; i < 16; i++) {
        const int id = tid + i * 128;
        const int p  = id >> 9;
        const int t  = (id >> 3) & 63;
        const int ci = id & 7;
        sQK[i] = g_qkv2 + (size_t)tok[t] * 2304 + p * 384 + ci * 8;
        dQK[i] = sb + (uint32_t)(p * 8192 + t * 128 + ((ci ^ (t & 7)) * 16));
    }

#define PREF_QK(cc) do {                                                      \
        const uint32_t _o = ((cc) & 1) * 32768u;                              \
        _Pragma("unroll")                                                     \
        for (int _i = 0; _i < 16; _i++) {                                     \
            asm volatile("cp.async.cg.shared.global [%0], [%1], 16;"          \
                :: "r"(dQK[_i] + _o), "l"(sQK[_i] + (cc) * 64));              \
        }                                                                     \
        asm volatile("cp.async.commit_group;" ::: "memory");                  \
    } while (0)

    float accS[8][4];
#pragma unroll
    for (int nt = 0; nt < 8; nt++)
#pragma unroll
        for (int i = 0; i < 4; i++) accS[nt][i] = 0.f;

    PREF_QK(0);

#pragma unroll
    for (int cc = 0; cc < 6; cc++) {
        asm volatile("cp.async.wait_group 0;" ::: "memory");
        __syncthreads();
        if (cc < 5) PREF_QK(cc + 1);
        const uint32_t st = (cc & 1) * 32768u;
        const uint32_t aQh = sb + st + (uint32_t)((wid * 16 + la) * 128);
        const uint32_t aQl = aQh + 8192;
        const uint32_t bKh = sb + st + 16384 + (uint32_t)(la * 128);
        const uint32_t bKl = bKh + 8192;
#pragma unroll
        for (int kt = 0; kt < 4; kt++) {
            uint32_t qh[4], ql[4];
            LDSM_X4(qh, aQh + coff[kt]);
            LDSM_X4(ql, aQl + coff[kt]);
#pragma unroll
            for (int ntp = 0; ntp < 4; ntp++) {
                uint32_t kh[4], kl[4];
                LDSM_X4(kh, bKh + ntp * 2048 + coff[kt]);
                LDSM_X4(kl, bKl + ntp * 2048 + coff[kt]);
                mma16816(accS[ntp * 2],     qh, kh[0], kh[2]);
                mma16816(accS[ntp * 2 + 1], qh, kh[1], kh[3]);
                mma16816(accS[ntp * 2],     ql, kh[0], kh[2]);
                mma16816(accS[ntp * 2 + 1], ql, kh[1], kh[3]);
                mma16816(accS[ntp * 2],     qh, kl[0], kl[2]);
                mma16816(accS[ntp * 2 + 1], qh, kl[1], kl[3]);
            }
        }
    }
#undef PREF_QK
    __syncthreads();

    {
        const int r0 = wid * 16 + g;
#pragma unroll
        for (int nt = 0; nt < 8; nt++) {
            const int col = nt * 8 + t4 * 2;
            Ss[r0][col]         = accS[nt][0];
            Ss[r0][col + 1]     = accS[nt][1];
            Ss[r0 + 8][col]     = accS[nt][2];
            Ss[r0 + 8][col + 1] = accS[nt][3];
        }
    }
    __syncthreads();

    if (tid < 64) {
        float m = -1e30f;
#pragma unroll 8
        for (int j = 0; j < 64; j++) m = fmaxf(m, Ss[tid][j]);
        float s = 0.f;
#pragma unroll 8
        for (int j = 0; j < 64; j++) {
            float e = expf(Ss[tid][j] - m);
            Ss[tid][j] = e;
            s += e;
        }
        float inv = 1.f / s;
#pragma unroll 8
        for (int j = 0; j < 64; j += 2) {
            uint32_t hh, ll;
            split2(Ss[tid][j] * inv, Ss[tid][j + 1] * inv, hh, ll);
            const int w = j >> 1;
            const uint32_t off = (uint32_t)(tid * 128 +
                (((w >> 2) ^ (tid & 7)) * 16) + (w & 3) * 4);
            *(uint32_t*)(asm_ + 65536 + off) = hh;
            *(uint32_t*)(asm_ + 73728 + off) = ll;
        }
    }
    __syncthreads();

    uint32_t ph[4][4], pl[4][4];
    const uint32_t aPh = sb + 65536 + (uint32_t)((wid * 16 + la) * 128);
#pragma unroll
    for (int kt = 0; kt < 4; kt++) {
        LDSM_X4(ph[kt], aPh + coff[kt]);
        LDSM_X4(pl[kt], aPh + 8192 + coff[kt]);
    }
    const int tr0 = tok[wid * 16 + g];
    const int tr1 = tok[wid * 16 + g + 8];

    const __nv_bfloat16* sV[8];
    uint32_t dV[8];
#pragma unroll
    for (int i = 0; i < 8; i++) {
        const int id = tid + i * 128;
        const int p  = id >> 9;
        const int t  = (id >> 3) & 63;
        const int ci = id & 7;
        sV[i] = g_qkv2 + (size_t)tok[t] * 2304 + 1536 + p * 384 + ci * 8;
        dV[i] = sb + (uint32_t)(p * 8192 + t * 128 + ((ci ^ (t & 7)) * 16));
    }

#define PREF_V(co) do {                                                       \
        const uint32_t _o = ((co) & 1) * 32768u;                              \
        _Pragma("unroll")                                                     \
        for (int _i = 0; _i < 8; _i++) {                                      \
            asm volatile("cp.async.cg.shared.global [%0], [%1], 16;"          \
                :: "r"(dV[_i] + _o), "l"(sV[_i] + (co) * 64));                \
        }                                                                     \
        asm volatile("cp.async.commit_group;" ::: "memory");                  \
    } while (0)

    PREF_V(0);

    const uint32_t vbase = sb + (uint32_t)(((((lane >> 3) & 1) * 8) + (lane & 7)) * 128);

#pragma unroll
    for (int co = 0; co < 6; co++) {
        asm volatile("cp.async.wait_group 0;" ::: "memory");
        __syncthreads();
        if (co < 5) PREF_V(co + 1);
        const uint32_t st = (co & 1) * 32768u;
        const uint32_t bVh = vbase + st;
        const uint32_t bVl = bVh + 8192;

        float accO[8][4];
#pragma unroll
        for (int nt = 0; nt < 8; nt++)
#pragma unroll
            for (int i = 0; i < 4; i++) accO[nt][i] = 0.f;

#pragma unroll
        for (int kt = 0; kt < 4; kt++) {
#pragma unroll
            for (int ntp = 0; ntp < 4; ntp++) {
                uint32_t vh[4], vl[4];
                LDSM_X4_T(vh, bVh + kt * 2048 + coff[ntp]);
                LDSM_X4_T(vl, bVl + kt * 2048 + coff[ntp]);
                mma16816(accO[ntp * 2],     ph[kt], vh[0], vh[1]);
                mma16816(accO[ntp * 2 + 1], ph[kt], vh[2], vh[3]);
                mma16816(accO[ntp * 2],     pl[kt], vh[0], vh[1]);
                mma16816(accO[ntp * 2 + 1], pl[kt], vh[2], vh[3]);
                mma16816(accO[ntp * 2],     ph[kt], vl[0], vl[1]);
                mma16816(accO[ntp * 2 + 1], ph[kt], vl[2], vl[3]);
            }
        }
#pragma unroll
        for (int nt = 0; nt < 8; nt++) {
            const int col = co * 64 + nt * 8 + t4 * 2;
            __half2 h0 = __floats2half2_rn(accO[nt][0], accO[nt][1]);
            __half2 h1 = __floats2half2_rn(accO[nt][2], accO[nt][3]);
            *(__half2*)(g_att_h + (size_t)tr0 * CDIM + col) = h0;
            *(__half2*)(g_att_h + (size_t)tr1 * CDIM + col) = h1;
        }
    }
#undef PREF_V
}

// ---------------------------------------------------------------------------
extern "C" void kernel_launch(void* const* d_in, const int* in_sizes, int n_in,
                              void* d_out, int out_size)
{
    const float* x      = (const float*)d_in[0];
    const float* w_qkv  = (const float*)d_in[1];
    const float* b_qkv  = (const float*)d_in[2];
    const float* w_proj = (const float*)d_in[3];
    const float* b_proj = (const float*)d_in[4];
    float* out = (float*)d_out;

    __nv_bfloat16* qkv2 = nullptr;
    __half *atth = nullptr, *xh = nullptr, *wt1 = nullptr, *wt3 = nullptr;
    cudaGetSymbolAddress((void**)&qkv2, g_qkv2);
    cudaGetSymbolAddress((void**)&atth, g_att_h);
    cudaGetSymbolAddress((void**)&xh,   g_xh);
    cudaGetSymbolAddress((void**)&wt1,  g_Wt1);
    cudaGetSymbolAddress((void**)&wt3,  g_Wt3);

    cudaFuncSetAttribute(gemm_h, cudaFuncAttributeMaxDynamicSharedMemorySize,
                         2 * STAGE_BYTES);
    cudaFuncSetAttribute(window_attn, cudaFuncAttributeMaxDynamicSharedMemorySize,
                         ATTN_SMEM);

    // Weight transposes + x conversion (cheap)
    trans_w_kernel<<<(NQKV * CDIM + 255) / 256, 256>>>(w_qkv, wt1, NQKV);
    trans_w_kernel<<<(CDIM * CDIM + 255) / 256, 256>>>(w_proj, wt3, CDIM);
    cvt_h_kernel<<<TOKENS * 96 / 256, 256>>>(x, xh);

    // K1: qkv = x @ w_qkv + b_qkv  -> split-bf16 planes (g_qkv2)
    gemm_h<<<dim3(NQKV / 64, TOKENS / 128), 256, 2 * STAGE_BYTES>>>(
        xh, wt1, b_qkv, nullptr, qkv2, NQKV);

    // K2: per-window attention (tensor S and PV) -> fp16 g_att_h
    window_attn<<<NWIN, 128, ATTN_SMEM>>>();

    // K3: out = att @ w_proj + b_proj (fp32 out)
    gemm_h<<<dim3(CDIM / 64, TOKENS / 128), 256, 2 * STAGE_BYTES>>>(
        atth, wt3, b_proj, out, nullptr, CDIM);
}

// round 13
// speedup vs baseline: 1.1949x; 1.1949x over previous
#include <cuda_runtime.h>
#include <cuda_bf16.h>
#include <cuda_fp16.h>
#include <cstdint>
#include <math.h>

// Problem constants (B=8, H=W=128, C=384, window=8)
#define TOKENS   131072              // 8*128*128
#define CDIM     384
#define NQKV     1152
#define NWIN     2048                // 8 * 16 * 16 windows

// ---------------------------------------------------------------------------
// Scratch (allocation-free rule: __device__ globals)
// g_qkv2 per-token (bf16): [q hi 384][q lo 384][k hi 384][k lo 384]
// g_vh   per-token (fp16): [v 384]
// ---------------------------------------------------------------------------
__device__ __nv_bfloat16 g_qkv2[(size_t)TOKENS * 1536];  // 402 MB
__device__ __half g_vh  [(size_t)TOKENS * CDIM];         // 100 MB
__device__ __half g_att_h[(size_t)TOKENS * CDIM];        // fp16 attention out
__device__ __half g_xh [(size_t)TOKENS * CDIM];          // fp16 x
__device__ __half g_Wt1[(size_t)NQKV * CDIM];            // w_qkv^T  fp16 [N][K]
__device__ __half g_Wt3[(size_t)CDIM * CDIM];            // w_proj^T fp16 [N][K]

__device__ __forceinline__ uint32_t smem_u32(const void* p) {
    uint32_t a;
    asm("{ .reg .u64 tmp; cvta.to.shared.u64 tmp, %1; cvt.u32.u64 %0, tmp; }"
        : "=r"(a) : "l"(p));
    return a;
}

// Split a float2 into packed bf16x2 hi and lo (residual) parts.
__device__ __forceinline__ void split2(float x, float y, uint32_t& hi, uint32_t& lo) {
    uint32_t h;
    asm("cvt.rn.bf16x2.f32 %0, %1, %2;" : "=r"(h) : "f"(y), "f"(x));
    float h0 = __uint_as_float(h << 16);
    float h1 = __uint_as_float(h & 0xffff0000u);
    float r0 = x - h0, r1 = y - h1;
    asm("cvt.rn.bf16x2.f32 %0, %1, %2;" : "=r"(lo) : "f"(r1), "f"(r0));
    hi = h;
}

// bf16 HMMA (attention S-phase — validated)
__device__ __forceinline__ void mma16816(float* c, const uint32_t* a,
                                         uint32_t b0, uint32_t b1) {
    asm volatile(
        "mma.sync.aligned.m16n8k16.row.col.f32.bf16.bf16.f32 "
        "{%0,%1,%2,%3}, {%4,%5,%6,%7}, {%8,%9}, {%0,%1,%2,%3};\n"
        : "+f"(c[0]), "+f"(c[1]), "+f"(c[2]), "+f"(c[3])
        : "r"(a[0]), "r"(a[1]), "r"(a[2]), "r"(a[3]), "r"(b0), "r"(b1));
}

// fp16 HMMA (GEMMs + attention O-phase)
__device__ __forceinline__ void mma16816h(float* c, const uint32_t* a,
                                          uint32_t b0, uint32_t b1) {
    asm volatile(
        "mma.sync.aligned.m16n8k16.row.col.f32.f16.f16.f32 "
        "{%0,%1,%2,%3}, {%4,%5,%6,%7}, {%8,%9}, {%0,%1,%2,%3};\n"
        : "+f"(c[0]), "+f"(c[1]), "+f"(c[2]), "+f"(c[3])
        : "r"(a[0]), "r"(a[1]), "r"(a[2]), "r"(a[3]), "r"(b0), "r"(b1));
}

#define LDSM_X4(r, a) \
    asm volatile("ldmatrix.sync.aligned.m8n8.x4.shared.b16 {%0,%1,%2,%3}, [%4];" \
        : "=r"((r)[0]), "=r"((r)[1]), "=r"((r)[2]), "=r"((r)[3]) : "r"(a))

#define LDSM_X4_T(r, a) \
    asm volatile("ldmatrix.sync.aligned.m8n8.x4.trans.shared.b16 {%0,%1,%2,%3}, [%4];" \
        : "=r"((r)[0]), "=r"((r)[1]), "=r"((r)[2]), "=r"((r)[3]) : "r"(a))

// ---------------------------------------------------------------------------
// Weight transpose -> fp16: w [384 x N] fp32 -> out [N x 384] fp16
// ---------------------------------------------------------------------------
__global__ __launch_bounds__(256) void trans_w_kernel(
    const float* __restrict__ w, __half* __restrict__ out, int N)
{
    const int t = blockIdx.x * 256 + threadIdx.x;
    if (t >= N * CDIM) return;
    const int n = t / CDIM;
    const int k = t % CDIM;
    out[(size_t)n * CDIM + k] = __float2half(w[(size_t)k * N + n]);
}

// ---------------------------------------------------------------------------
// fp32 -> fp16 bulk convert (x)
// ---------------------------------------------------------------------------
__global__ __launch_bounds__(256) void cvt_h_kernel(
    const float* __restrict__ in, __half* __restrict__ out)
{
    const size_t t = (size_t)blockIdx.x * 256 + threadIdx.x;   // < TOKENS*96
    float4 v = *(const float4*)(in + t * 4);
    __half2 a = __floats2half2_rn(v.x, v.y);
    __half2 b = __floats2half2_rn(v.z, v.w);
    *(uint2*)(out + t * 4) = make_uint2(*(uint32_t*)&a, *(uint32_t*)&b);
}

// ---------------------------------------------------------------------------
// fp16 GEMM (r11 config, validated): BM=128, BN=128, BK=64, 8 warps 4Mx2N,
// 3 stages x 32KB, 2 CTAs/SM.
// Csplit path (K1): q/k sections -> smem-staged split-bf16 coalesced stores;
//                   v section    -> smem-staged fp16 coalesced stores (Vout).
// ---------------------------------------------------------------------------
#define STAGE_BYTES 32768u
__global__ __launch_bounds__(256, 2) void gemm_h(
    const __half* __restrict__ A,
    const __half* __restrict__ Bt,
    const float* __restrict__ bias,
    float* __restrict__ C,
    __nv_bfloat16* __restrict__ Csplit,
    __half* __restrict__ Vout,
    int Ndim)
{
    extern __shared__ __align__(16) char smem[];
    const uint32_t smemBase = smem_u32(smem);

    const int tid  = threadIdx.x;
    const int wid  = tid >> 5;
    const int lane = tid & 31;
    const int g    = lane >> 2;
    const int t4   = lane & 3;
    const int m0   = blockIdx.y * 128;
    const int n0   = blockIdx.x * 128;
    const int wm   = (wid & 3) * 32;
    const int wn   = (wid >> 2) * 64;

    // cp.async: 2048 chunks of 16B per stage (A 1024 + B 1024); 8 per thread
    const __half* srcs[8];
    uint32_t dsts[8];
#pragma unroll
    for (int i = 0; i < 8; i++) {
        const int id = tid + i * 256;
        const int ab = id >> 10;
        const int r  = (id >> 3) & 127;
        const int ch = id & 7;
        if (ab == 0) srcs[i] = A  + (size_t)(m0 + r) * CDIM + ch * 8;
        else         srcs[i] = Bt + (size_t)(n0 + r) * CDIM + ch * 8;
        dsts[i] = smemBase + (uint32_t)(ab * 16384 + r * 128 + ((ch ^ (r & 7)) * 16));
    }

#define PREFETCH(s, off) do {                                                 \
        _Pragma("unroll")                                                     \
        for (int _i = 0; _i < 8; _i++) {                                      \
            asm volatile("cp.async.cg.shared.global [%0], [%1], 16;"          \
                :: "r"(dsts[_i] + (off)), "l"(srcs[_i] + (s) * 64));          \
        }                                                                     \
        asm volatile("cp.async.commit_group;" ::: "memory");                  \
    } while (0)

    const int la = lane & 15;
    const int h  = lane >> 4;
    const int s7 = la & 7;
    uint32_t coff[4];
#pragma unroll
    for (int q = 0; q < 4; q++)
        coff[q] = (uint32_t)((((2 * q + h) ^ s7) & 7) * 16);
    const uint32_t aBase = smemBase + (uint32_t)((wm + la) * 128);
    const uint32_t bBase = smemBase + 16384 + (uint32_t)((wn + la) * 128);

    float acc[2][8][4];
#pragma unroll
    for (int mt = 0; mt < 2; mt++)
#pragma unroll
        for (int nt = 0; nt < 8; nt++)
#pragma unroll
            for (int i = 0; i < 4; i++) acc[mt][nt][i] = 0.f;

    PREFETCH(0, 0);
    PREFETCH(1, STAGE_BYTES);

#pragma unroll
    for (int s = 0; s < 6; s++) {
        asm volatile("cp.async.wait_group 1;" ::: "memory");
        __syncthreads();
        if (s < 4) PREFETCH(s + 2, ((s + 2) % 3) * STAGE_BYTES);
        else asm volatile("cp.async.commit_group;" ::: "memory");
        const uint32_t off = (s % 3) * STAGE_BYTES;

#pragma unroll
        for (int q = 0; q < 4; q++) {              // 4 x k16 per stage
            uint32_t a[2][4];
#pragma unroll
            for (int mt = 0; mt < 2; mt++)
                LDSM_X4(a[mt], aBase + off + mt * 2048 + coff[q]);
#pragma unroll
            for (int ntp = 0; ntp < 4; ntp++) {
                uint32_t b[4];
                LDSM_X4(b, bBase + off + ntp * 2048 + coff[q]);
                mma16816h(acc[0][ntp * 2],     a[0], b[0], b[2]);
                mma16816h(acc[0][ntp * 2 + 1], a[0], b[1], b[3]);
                mma16816h(acc[1][ntp * 2],     a[1], b[0], b[2]);
                mma16816h(acc[1][ntp * 2 + 1], a[1], b[1], b[3]);
            }
        }
    }
#undef PREFETCH

    if (Csplit) {
        // --- staged, coalesced epilogue (K1 path) ---
        __syncthreads();   // all warps done reading pipeline smem
        const int sec = blockIdx.x / 3;        // 0=q, 1=k, 2=v
        const int wi  = (blockIdx.x % 3) * 128;
        if (sec < 2) {
            // split-bf16: hi plane @0, lo plane @34816; 272B row stride
#pragma unroll
            for (int mt = 0; mt < 2; mt++) {
                const int lr = wm + mt * 16 + g;
#pragma unroll
                for (int nt = 0; nt < 8; nt++) {
                    const int cl = wn + (nt >> 1) * 16 + (nt & 1) * 8 + t4 * 2;
                    float2 bv = *(const float2*)(bias + n0 + cl);
                    uint32_t hh, ll;
                    split2(acc[mt][nt][0] + bv.x, acc[mt][nt][1] + bv.y, hh, ll);
                    *(uint32_t*)(smem + lr * 272 + cl * 2) = hh;
                    *(uint32_t*)(smem + 34816 + lr * 272 + cl * 2) = ll;
                    split2(acc[mt][nt][2] + bv.x, acc[mt][nt][3] + bv.y, hh, ll);
                    *(uint32_t*)(smem + (lr + 8) * 272 + cl * 2) = hh;
                    *(uint32_t*)(smem + 34816 + (lr + 8) * 272 + cl * 2) = ll;
                }
            }
            __syncthreads();
            __nv_bfloat16* gb = Csplit + (size_t)m0 * 1536 + sec * 768 + wi;
#pragma unroll
            for (int i = 0; i < 16; i++) {
                const int id = tid + i * 256;    // < 4096
                const int t  = id >> 5;
                const int ch = id & 31;
                *(uint2*)(gb + (size_t)t * 1536 + ch * 4) =
                    *(uint2*)(smem + t * 272 + ch * 8);
                *(uint2*)(gb + (size_t)t * 1536 + 384 + ch * 4) =
                    *(uint2*)(smem + 34816 + t * 272 + ch * 8);
            }
        } else {
            // V: fp16 single plane
#pragma unroll
            for (int mt = 0; mt < 2; mt++) {
                const int lr = wm + mt * 16 + g;
#pragma unroll
                for (int nt = 0; nt < 8; nt++) {
                    const int cl = wn + (nt >> 1) * 16 + (nt & 1) * 8 + t4 * 2;
                    float2 bv = *(const float2*)(bias + n0 + cl);
                    __half2 h0 = __floats2half2_rn(acc[mt][nt][0] + bv.x,
                                                   acc[mt][nt][1] + bv.y);
                    __half2 h1 = __floats2half2_rn(acc[mt][nt][2] + bv.x,
                                                   acc[mt][nt][3] + bv.y);
                    *(uint32_t*)(smem + lr * 272 + cl * 2) = *(uint32_t*)&h0;
                    *(uint32_t*)(smem + (lr + 8) * 272 + cl * 2) = *(uint32_t*)&h1;
                }
            }
            __syncthreads();
            __half* gv = Vout + (size_t)m0 * CDIM + wi;
#pragma unroll
            for (int i = 0; i < 16; i++) {
                const int id = tid + i * 256;
                const int t  = id >> 5;
                const int ch = id & 31;
                *(uint2*)(gv + (size_t)t * CDIM + ch * 4) =
                    *(uint2*)(smem + t * 272 + ch * 8);
            }
        }
    } else {
        // --- fp32 epilogue (K3 path, unchanged) ---
#pragma unroll
        for (int mt = 0; mt < 2; mt++) {
            const int r0 = m0 + wm + mt * 16 + g;
#pragma unroll
            for (int nt = 0; nt < 8; nt++) {
                const int col = n0 + wn + (nt >> 1) * 16 + (nt & 1) * 8 + t4 * 2;
                float2 bv = *(const float2*)(bias + col);
                float2 v0 = make_float2(acc[mt][nt][0] + bv.x, acc[mt][nt][1] + bv.y);
                float2 v1 = make_float2(acc[mt][nt][2] + bv.x, acc[mt][nt][3] + bv.y);
                *(float2*)(C + (size_t)r0 * Ndim + col) = v0;
                *(float2*)(C + (size_t)(r0 + 8) * Ndim + col) = v1;
            }
        }
    }
}

// ---------------------------------------------------------------------------
// Window attention: S-phase split-bf16 (validated), O-phase fp16 single-pass.
//   smem: S stages [0,64K) (2 x 32KB: Qh|Ql|Kh|Kl 8KB each);
//         V stages reuse slot-0 region of each stage (8KB used);
//         P fp16 plane @65536 (8KB); Ss fp32 overlays stage0; tok @81920.
// ---------------------------------------------------------------------------
#define ATTN_SMEM 82432
__global__ __launch_bounds__(128) void window_attn()
{
    extern __shared__ __align__(16) char asm_[];
    const uint32_t sb = smem_u32(asm_);
    int* tok = (int*)(asm_ + 81920);
    float (*Ss)[65] = (float(*)[65])asm_;

    const int gb = blockIdx.x;
    const int b = gb >> 8, win = gb & 255, wy = win >> 4, wx = win & 15;
    const int tid = threadIdx.x;
    if (tid < 64) {
        int py = tid >> 3, px = tid & 7;
        tok[tid] = b * 16384 + (wy * 8 + py) * 128 + (wx * 8 + px);
    }
    __syncthreads();

    const int wid = tid >> 5, lane = tid & 31;
    const int g = lane >> 2, t4 = lane & 3;
    const int la = lane & 15, lh = lane >> 4;

    uint32_t coff[4];
#pragma unroll
    for (int q = 0; q < 4; q++)
        coff[q] = (uint32_t)((((2 * q + lh) ^ (lane & 7)) & 7) * 16);

    // ---- S-phase cp.async descriptors (4 planes: Qh Ql Kh Kl) ----
    const __nv_bfloat16* sQK[16];
    uint32_t dQK[16];
#pragma unroll
    for (int i = 0; i < 16; i++) {
        const int id = tid + i * 128;
        const int p  = id >> 9;
        const int t  = (id >> 3) & 63;
        const int ci = id & 7;
        sQK[i] = g_qkv2 + (size_t)tok[t] * 1536 + p * 384 + ci * 8;
        dQK[i] = sb + (uint32_t)(p * 8192 + t * 128 + ((ci ^ (t & 7)) * 16));
    }

#define PREF_QK(cc) do {                                                      \
        const uint32_t _o = ((cc) & 1) * 32768u;                              \
        _Pragma("unroll")                                                     \
        for (int _i = 0; _i < 16; _i++) {                                     \
            asm volatile("cp.async.cg.shared.global [%0], [%1], 16;"          \
                :: "r"(dQK[_i] + _o), "l"(sQK[_i] + (cc) * 64));              \
        }                                                                     \
        asm volatile("cp.async.commit_group;" ::: "memory");                  \
    } while (0)

    float accS[8][4];
#pragma unroll
    for (int nt = 0; nt < 8; nt++)
#pragma unroll
        for (int i = 0; i < 4; i++) accS[nt][i] = 0.f;

    PREF_QK(0);

#pragma unroll
    for (int cc = 0; cc < 6; cc++) {
        asm volatile("cp.async.wait_group 0;" ::: "memory");
        __syncthreads();
        if (cc < 5) PREF_QK(cc + 1);
        const uint32_t st = (cc & 1) * 32768u;
        const uint32_t aQh = sb + st + (uint32_t)((wid * 16 + la) * 128);
        const uint32_t aQl = aQh + 8192;
        const uint32_t bKh = sb + st + 16384 + (uint32_t)(la * 128);
        const uint32_t bKl = bKh + 8192;
#pragma unroll
        for (int kt = 0; kt < 4; kt++) {
            uint32_t qh[4], ql[4];
            LDSM_X4(qh, aQh + coff[kt]);
            LDSM_X4(ql, aQl + coff[kt]);
#pragma unroll
            for (int ntp = 0; ntp < 4; ntp++) {
                uint32_t kh[4], kl[4];
                LDSM_X4(kh, bKh + ntp * 2048 + coff[kt]);
                LDSM_X4(kl, bKl + ntp * 2048 + coff[kt]);
                mma16816(accS[ntp * 2],     qh, kh[0], kh[2]);
                mma16816(accS[ntp * 2 + 1], qh, kh[1], kh[3]);
                mma16816(accS[ntp * 2],     ql, kh[0], kh[2]);
                mma16816(accS[ntp * 2 + 1], ql, kh[1], kh[3]);
                mma16816(accS[ntp * 2],     qh, kl[0], kl[2]);
                mma16816(accS[ntp * 2 + 1], qh, kl[1], kl[3]);
            }
        }
    }
#undef PREF_QK
    __syncthreads();

    // ---- S -> Ss (fp32, overlays stage0) ----
    {
        const int r0 = wid * 16 + g;
#pragma unroll
        for (int nt = 0; nt < 8; nt++) {
            const int col = nt * 8 + t4 * 2;
            Ss[r0][col]         = accS[nt][0];
            Ss[r0][col + 1]     = accS[nt][1];
            Ss[r0 + 8][col]     = accS[nt][2];
            Ss[r0 + 8][col + 1] = accS[nt][3];
        }
    }
    __syncthreads();

    // ---- softmax (fp32) + P -> fp16 plane @65536 ----
    if (tid < 64) {
        float m = -1e30f;
#pragma unroll 8
        for (int j = 0; j < 64; j++) m = fmaxf(m, Ss[tid][j]);
        float s = 0.f;
#pragma unroll 8
        for (int j = 0; j < 64; j++) {
            float e = expf(Ss[tid][j] - m);
            Ss[tid][j] = e;
            s += e;
        }
        float inv = 1.f / s;
#pragma unroll 8
        for (int j = 0; j < 64; j += 2) {
            __half2 p2 = __floats2half2_rn(Ss[tid][j] * inv, Ss[tid][j + 1] * inv);
            const int w = j >> 1;
            const uint32_t off = (uint32_t)(tid * 128 +
                (((w >> 2) ^ (tid & 7)) * 16) + (w & 3) * 4);
            *(uint32_t*)(asm_ + 65536 + off) = *(uint32_t*)&p2;
        }
    }
    __syncthreads();

    // ---- P fragments (fp16, loop-invariant) ----
    uint32_t ph[4][4];
    const uint32_t aPh = sb + 65536 + (uint32_t)((wid * 16 + la) * 128);
#pragma unroll
    for (int kt = 0; kt < 4; kt++)
        LDSM_X4(ph[kt], aPh + coff[kt]);
    const int tr0 = tok[wid * 16 + g];
    const int tr1 = tok[wid * 16 + g + 8];

    // ---- O-phase cp.async descriptors (V fp16 single plane) ----
    const __half* sV[4];
    uint32_t dV[4];
#pragma unroll
    for (int i = 0; i < 4; i++) {
        const int id = tid + i * 128;          // < 512
        const int t  = id >> 3;
        const int ci = id & 7;
        sV[i] = g_vh + (size_t)tok[t] * CDIM + ci * 8;
        dV[i] = sb + (uint32_t)(t * 128 + ((ci ^ (t & 7)) * 16));
    }

#define PREF_V(co) do {                                                       \
        const uint32_t _o = ((co) & 1) * 32768u;                              \
        _Pragma("unroll")                                                     \
        for (int _i = 0; _i < 4; _i++) {                                      \
            asm volatile("cp.async.cg.shared.global [%0], [%1], 16;"          \
                :: "r"(dV[_i] + _o), "l"(sV[_i] + (co) * 64));                \
        }                                                                     \
        asm volatile("cp.async.commit_group;" ::: "memory");                  \
    } while (0)

    PREF_V(0);

    const uint32_t vbase = sb + (uint32_t)(((((lane >> 3) & 1) * 8) + (lane & 7)) * 128);

#pragma unroll
    for (int co = 0; co < 6; co++) {
        asm volatile("cp.async.wait_group 0;" ::: "memory");
        __syncthreads();
        if (co < 5) PREF_V(co + 1);
        const uint32_t bVh = vbase + (co & 1) * 32768u;

        float accO[8][4];
#pragma unroll
        for (int nt = 0; nt < 8; nt++)
#pragma unroll
            for (int i = 0; i < 4; i++) accO[nt][i] = 0.f;

#pragma unroll
        for (int kt = 0; kt < 4; kt++) {
#pragma unroll
            for (int ntp = 0; ntp < 4; ntp++) {
                uint32_t vh[4];
                LDSM_X4_T(vh, bVh + kt * 2048 + coff[ntp]);
                mma16816h(accO[ntp * 2],     ph[kt], vh[0], vh[1]);
                mma16816h(accO[ntp * 2 + 1], ph[kt], vh[2], vh[3]);
            }
        }
#pragma unroll
        for (int nt = 0; nt < 8; nt++) {
            const int col = co * 64 + nt * 8 + t4 * 2;
            __half2 h0 = __floats2half2_rn(accO[nt][0], accO[nt][1]);
            __half2 h1 = __floats2half2_rn(accO[nt][2], accO[nt][3]);
            *(__half2*)(g_att_h + (size_t)tr0 * CDIM + col) = h0;
            *(__half2*)(g_att_h + (size_t)tr1 * CDIM + col) = h1;
        }
    }
#undef PREF_V
}

// ---------------------------------------------------------------------------
extern "C" void kernel_launch(void* const* d_in, const int* in_sizes, int n_in,
                              void* d_out, int out_size)
{
    const float* x      = (const float*)d_in[0];
    const float* w_qkv  = (const float*)d_in[1];
    const float* b_qkv  = (const float*)d_in[2];
    const float* w_proj = (const float*)d_in[3];
    const float* b_proj = (const float*)d_in[4];
    float* out = (float*)d_out;

    __nv_bfloat16* qkv2 = nullptr;
    __half *vh = nullptr, *atth = nullptr, *xh = nullptr, *wt1 = nullptr, *wt3 = nullptr;
    cudaGetSymbolAddress((void**)&qkv2, g_qkv2);
    cudaGetSymbolAddress((void**)&vh,   g_vh);
    cudaGetSymbolAddress((void**)&atth, g_att_h);
    cudaGetSymbolAddress((void**)&xh,   g_xh);
    cudaGetSymbolAddress((void**)&wt1,  g_Wt1);
    cudaGetSymbolAddress((void**)&wt3,  g_Wt3);

    cudaFuncSetAttribute(gemm_h, cudaFuncAttributeMaxDynamicSharedMemorySize,
                         3 * STAGE_BYTES);
    cudaFuncSetAttribute(window_attn, cudaFuncAttributeMaxDynamicSharedMemorySize,
                         ATTN_SMEM);

    // Weight transposes + x conversion (cheap)
    trans_w_kernel<<<(NQKV * CDIM + 255) / 256, 256>>>(w_qkv, wt1, NQKV);
    trans_w_kernel<<<(CDIM * CDIM + 255) / 256, 256>>>(w_proj, wt3, CDIM);
    cvt_h_kernel<<<TOKENS * 96 / 256, 256>>>(x, xh);

    // K1: qkv = x @ w_qkv + b_qkv  -> split-bf16 q/k planes + fp16 v
    gemm_h<<<dim3(NQKV / 128, TOKENS / 128), 256, 3 * STAGE_BYTES>>>(
        xh, wt1, b_qkv, nullptr, qkv2, vh, NQKV);

    // K2: per-window attention -> fp16 g_att_h
    window_attn<<<NWIN, 128, ATTN_SMEM>>>();

    // K3: out = att @ w_proj + b_proj (fp32 out)
    gemm_h<<<dim3(CDIM / 128, TOKENS / 128), 256, 3 * STAGE_BYTES>>>(
        atth, wt3, b_proj, out, nullptr, nullptr, CDIM);
}

// round 14
// speedup vs baseline: 1.3050x; 1.0921x over previous
#include <cuda_runtime.h>
#include <cuda_bf16.h>
#include <cuda_fp16.h>
#include <cstdint>
#include <math.h>

// Problem constants (B=8, H=W=128, C=384, window=8)
#define TOKENS   131072              // 8*128*128
#define CDIM     384
#define NQKV     1152
#define NWIN     2048                // 8 * 16 * 16 windows

// ---------------------------------------------------------------------------
// Scratch (allocation-free rule: __device__ globals)
// ---------------------------------------------------------------------------
__device__ __half        g_Mcat[768 * CDIM];              // [M1^T ; M2^T] fp16
__device__ float         g_w1[CDIM];                      // Wk·b_q
__device__ float         g_Bout[CDIM];                    // b_v·Wp + b_p
__device__ __half        g_xh[(size_t)TOKENS * CDIM];     // x fp16 (GEMM A)
__device__ __nv_bfloat16 g_xs[(size_t)TOKENS * 768];      // x split planes [hi|lo]
__device__ float         g_c [(size_t)TOKENS];            // S column bias
__device__ __nv_bfloat16 g_y [(size_t)TOKENS * 768];      // Y split planes [hi|lo]
__device__ __half        g_u [(size_t)TOKENS * CDIM];     // u = x·M2 fp16

__device__ __forceinline__ uint32_t smem_u32(const void* p) {
    uint32_t a;
    asm("{ .reg .u64 tmp; cvta.to.shared.u64 tmp, %1; cvt.u32.u64 %0, tmp; }"
        : "=r"(a) : "l"(p));
    return a;
}

// Split a float2 into packed bf16x2 hi and lo (residual) parts.
__device__ __forceinline__ void split2(float x, float y, uint32_t& hi, uint32_t& lo) {
    uint32_t h;
    asm("cvt.rn.bf16x2.f32 %0, %1, %2;" : "=r"(h) : "f"(y), "f"(x));
    float h0 = __uint_as_float(h << 16);
    float h1 = __uint_as_float(h & 0xffff0000u);
    float r0 = x - h0, r1 = y - h1;
    asm("cvt.rn.bf16x2.f32 %0, %1, %2;" : "=r"(lo) : "f"(r1), "f"(r0));
    hi = h;
}

// bf16 HMMA (attention S-phase)
__device__ __forceinline__ void mma16816(float* c, const uint32_t* a,
                                         uint32_t b0, uint32_t b1) {
    asm volatile(
        "mma.sync.aligned.m16n8k16.row.col.f32.bf16.bf16.f32 "
        "{%0,%1,%2,%3}, {%4,%5,%6,%7}, {%8,%9}, {%0,%1,%2,%3};\n"
        : "+f"(c[0]), "+f"(c[1]), "+f"(c[2]), "+f"(c[3])
        : "r"(a[0]), "r"(a[1]), "r"(a[2]), "r"(a[3]), "r"(b0), "r"(b1));
}

// fp16 HMMA (GEMM + attention O-phase)
__device__ __forceinline__ void mma16816h(float* c, const uint32_t* a,
                                          uint32_t b0, uint32_t b1) {
    asm volatile(
        "mma.sync.aligned.m16n8k16.row.col.f32.f16.f16.f32 "
        "{%0,%1,%2,%3}, {%4,%5,%6,%7}, {%8,%9}, {%0,%1,%2,%3};\n"
        : "+f"(c[0]), "+f"(c[1]), "+f"(c[2]), "+f"(c[3])
        : "r"(a[0]), "r"(a[1]), "r"(a[2]), "r"(a[3]), "r"(b0), "r"(b1));
}

#define LDSM_X4(r, a) \
    asm volatile("ldmatrix.sync.aligned.m8n8.x4.shared.b16 {%0,%1,%2,%3}, [%4];" \
        : "=r"((r)[0]), "=r"((r)[1]), "=r"((r)[2]), "=r"((r)[3]) : "r"(a))

#define LDSM_X4_T(r, a) \
    asm volatile("ldmatrix.sync.aligned.m8n8.x4.trans.shared.b16 {%0,%1,%2,%3}, [%4];" \
        : "=r"((r)[0]), "=r"((r)[1]), "=r"((r)[2]), "=r"((r)[3]) : "r"(a))

// ---------------------------------------------------------------------------
// Small fp32 GEMM -> fp16: C[m0out+m][n] = sum_c A[m*saR+c*saC]*B[n*sbR+c*sbC]
// 64x64 tiles, K=384. Used for M1^T and M2^T (into g_Mcat).
// ---------------------------------------------------------------------------
__global__ __launch_bounds__(256) void small_gemm(
    const float* __restrict__ A, const float* __restrict__ B,
    __half* __restrict__ Cc, int m0out,
    int saR, int saC, int sbR, int sbC)
{
    __shared__ float As[16][68], Bs[16][68];
    const int tid = threadIdx.x;
    const int tx = tid & 15, ty = tid >> 4;
    const int bm = blockIdx.y * 64, bn = blockIdx.x * 64;
    float acc[4][4];
#pragma unroll
    for (int i = 0; i < 4; i++)
#pragma unroll
        for (int j = 0; j < 4; j++) acc[i][j] = 0.f;

    for (int k0 = 0; k0 < CDIM; k0 += 16) {
#pragma unroll
        for (int i = 0; i < 4; i++) {
            const int id = tid + i * 256;
            const int m = id & 63, k = id >> 6;
            As[k][m] = A[(size_t)(bm + m) * saR + (size_t)(k0 + k) * saC];
            Bs[k][m] = B[(size_t)(bn + m) * sbR + (size_t)(k0 + k) * sbC];
        }
        __syncthreads();
#pragma unroll
        for (int k = 0; k < 16; k++)
#pragma unroll
            for (int i = 0; i < 4; i++)
#pragma unroll
                for (int j = 0; j < 4; j++)
                    acc[i][j] += As[k][ty * 4 + i] * Bs[k][tx * 4 + j];
        __syncthreads();
    }
#pragma unroll
    for (int i = 0; i < 4; i++)
#pragma unroll
        for (int j = 0; j < 4; j++)
            Cc[(size_t)(m0out + bm + ty * 4 + i) * CDIM + bn + tx * 4 + j] =
                __float2half(acc[i][j]);
}

// ---------------------------------------------------------------------------
// Bias vectors: w1[a] = sum_c W[a][384+c]*b_q[c];  Bout[n] = b_v·Wp + b_p
// ---------------------------------------------------------------------------
__global__ __launch_bounds__(256) void bias_vec(
    const float* __restrict__ w_qkv, const float* __restrict__ b_qkv,
    const float* __restrict__ w_proj, const float* __restrict__ b_proj)
{
    const int t = blockIdx.x * 256 + threadIdx.x;
    if (t < CDIM) {
        float s = 0.f;
        for (int c = 0; c < CDIM; c++)
            s += w_qkv[(size_t)t * NQKV + 384 + c] * b_qkv[c];
        g_w1[t] = s;
    } else if (t < 2 * CDIM) {
        const int n = t - CDIM;
        float s = 0.f;
        for (int c = 0; c < CDIM; c++)
            s += b_qkv[768 + c] * w_proj[(size_t)c * CDIM + n];
        g_Bout[n] = s + b_proj[n];
    }
}

// ---------------------------------------------------------------------------
// x -> fp16 (g_xh) + split-bf16 planes (g_xs) + column bias c = x·w1 (g_c)
// 8 threads per token row; 4096 blocks x 256 threads.
// ---------------------------------------------------------------------------
__global__ __launch_bounds__(256) void cvt_split(const float* __restrict__ x)
{
    __shared__ float w1s[CDIM];
    for (int i = threadIdx.x; i < CDIM; i += 256) w1s[i] = g_w1[i];
    __syncthreads();

    const int row = blockIdx.x * 32 + (threadIdx.x >> 3);
    const int j   = threadIdx.x & 7;
    const float* xr = x + (size_t)row * CDIM;
    float dot = 0.f;
#pragma unroll
    for (int k = 0; k < 12; k++) {
        const int col = j * 4 + k * 32;
        float4 v = *(const float4*)(xr + col);
        __half2 a = __floats2half2_rn(v.x, v.y);
        __half2 b = __floats2half2_rn(v.z, v.w);
        *(uint2*)(g_xh + (size_t)row * CDIM + col) =
            make_uint2(*(uint32_t*)&a, *(uint32_t*)&b);
        uint32_t h0, l0, h1, l1;
        split2(v.x, v.y, h0, l0);
        split2(v.z, v.w, h1, l1);
        *(uint2*)(g_xs + (size_t)row * 768 + col)       = make_uint2(h0, h1);
        *(uint2*)(g_xs + (size_t)row * 768 + 384 + col) = make_uint2(l0, l1);
        dot += v.x * w1s[col] + v.y * w1s[col + 1]
             + v.z * w1s[col + 2] + v.w * w1s[col + 3];
    }
#pragma unroll
    for (int o = 4; o > 0; o >>= 1) dot += __shfl_down_sync(0xffffffffu, dot, o, 8);
    if (j == 0) g_c[row] = dot;
}

// ---------------------------------------------------------------------------
// Fused GEMM: [Y|u] = x(fp16) @ Mcat^T.  BM=128, BN=128, BK=64, 8 warps 4Mx2N,
// 3 stages x 32KB, 2 CTAs/SM. grid (6, 1024); blockIdx.x<3 -> Y split-bf16,
// else -> u fp16.  No bias (all bias terms handled analytically).
// ---------------------------------------------------------------------------
#define STAGE_BYTES 32768u
__global__ __launch_bounds__(256, 2) void gemm_fused()
{
    extern __shared__ __align__(16) char smem[];
    const uint32_t smemBase = smem_u32(smem);

    const int tid  = threadIdx.x;
    const int wid  = tid >> 5;
    const int lane = tid & 31;
    const int g    = lane >> 2;
    const int t4   = lane & 3;
    const int m0   = blockIdx.y * 128;
    const int n0   = blockIdx.x * 128;
    const int wm   = (wid & 3) * 32;
    const int wn   = (wid >> 2) * 64;

    const __half* srcs[8];
    uint32_t dsts[8];
#pragma unroll
    for (int i = 0; i < 8; i++) {
        const int id = tid + i * 256;
        const int ab = id >> 10;
        const int r  = (id >> 3) & 127;
        const int ch = id & 7;
        if (ab == 0) srcs[i] = g_xh   + (size_t)(m0 + r) * CDIM + ch * 8;
        else         srcs[i] = g_Mcat + (size_t)(n0 + r) * CDIM + ch * 8;
        dsts[i] = smemBase + (uint32_t)(ab * 16384 + r * 128 + ((ch ^ (r & 7)) * 16));
    }

#define PREFETCH(s, off) do {                                                 \
        _Pragma("unroll")                                                     \
        for (int _i = 0; _i < 8; _i++) {                                      \
            asm volatile("cp.async.cg.shared.global [%0], [%1], 16;"          \
                :: "r"(dsts[_i] + (off)), "l"(srcs[_i] + (s) * 64));          \
        }                                                                     \
        asm volatile("cp.async.commit_group;" ::: "memory");                  \
    } while (0)

    const int la = lane & 15;
    const int h  = lane >> 4;
    const int s7 = la & 7;
    uint32_t coff[4];
#pragma unroll
    for (int q = 0; q < 4; q++)
        coff[q] = (uint32_t)((((2 * q + h) ^ s7) & 7) * 16);
    const uint32_t aBase = smemBase + (uint32_t)((wm + la) * 128);
    const uint32_t bBase = smemBase + 16384 + (uint32_t)((wn + la) * 128);

    float acc[2][8][4];
#pragma unroll
    for (int mt = 0; mt < 2; mt++)
#pragma unroll
        for (int nt = 0; nt < 8; nt++)
#pragma unroll
            for (int i = 0; i < 4; i++) acc[mt][nt][i] = 0.f;

    PREFETCH(0, 0);
    PREFETCH(1, STAGE_BYTES);

#pragma unroll
    for (int s = 0; s < 6; s++) {
        asm volatile("cp.async.wait_group 1;" ::: "memory");
        __syncthreads();
        if (s < 4) PREFETCH(s + 2, ((s + 2) % 3) * STAGE_BYTES);
        else asm volatile("cp.async.commit_group;" ::: "memory");
        const uint32_t off = (s % 3) * STAGE_BYTES;

#pragma unroll
        for (int q = 0; q < 4; q++) {
            uint32_t a[2][4];
#pragma unroll
            for (int mt = 0; mt < 2; mt++)
                LDSM_X4(a[mt], aBase + off + mt * 2048 + coff[q]);
#pragma unroll
            for (int ntp = 0; ntp < 4; ntp++) {
                uint32_t b[4];
                LDSM_X4(b, bBase + off + ntp * 2048 + coff[q]);
                mma16816h(acc[0][ntp * 2],     a[0], b[0], b[2]);
                mma16816h(acc[0][ntp * 2 + 1], a[0], b[1], b[3]);
                mma16816h(acc[1][ntp * 2],     a[1], b[0], b[2]);
                mma16816h(acc[1][ntp * 2 + 1], a[1], b[1], b[3]);
            }
        }
    }
#undef PREFETCH

    // --- staged, coalesced epilogue ---
    __syncthreads();
    if (blockIdx.x < 3) {
        // Y -> split-bf16 planes; smem: hi @0, lo @34816, 272B row stride
        const int wi = blockIdx.x * 128;
#pragma unroll
        for (int mt = 0; mt < 2; mt++) {
            const int lr = wm + mt * 16 + g;
#pragma unroll
            for (int nt = 0; nt < 8; nt++) {
                const int cl = wn + (nt >> 1) * 16 + (nt & 1) * 8 + t4 * 2;
                uint32_t hh, ll;
                split2(acc[mt][nt][0], acc[mt][nt][1], hh, ll);
                *(uint32_t*)(smem + lr * 272 + cl * 2) = hh;
                *(uint32_t*)(smem + 34816 + lr * 272 + cl * 2) = ll;
                split2(acc[mt][nt][2], acc[mt][nt][3], hh, ll);
                *(uint32_t*)(smem + (lr + 8) * 272 + cl * 2) = hh;
                *(uint32_t*)(smem + 34816 + (lr + 8) * 272 + cl * 2) = ll;
            }
        }
        __syncthreads();
        __nv_bfloat16* gb = g_y + (size_t)m0 * 768 + wi;
#pragma unroll
        for (int i = 0; i < 16; i++) {
            const int id = tid + i * 256;
            const int t  = id >> 5;
            const int ch = id & 31;
            *(uint2*)(gb + (size_t)t * 768 + ch * 4) =
                *(uint2*)(smem + t * 272 + ch * 8);
            *(uint2*)(gb + (size_t)t * 768 + 384 + ch * 4) =
                *(uint2*)(smem + 34816 + t * 272 + ch * 8);
        }
    } else {
        // u -> fp16 plane
        const int wi = (blockIdx.x - 3) * 128;
#pragma unroll
        for (int mt = 0; mt < 2; mt++) {
            const int lr = wm + mt * 16 + g;
#pragma unroll
            for (int nt = 0; nt < 8; nt++) {
                const int cl = wn + (nt >> 1) * 16 + (nt & 1) * 8 + t4 * 2;
                __half2 h0 = __floats2half2_rn(acc[mt][nt][0], acc[mt][nt][1]);
                __half2 h1 = __floats2half2_rn(acc[mt][nt][2], acc[mt][nt][3]);
                *(uint32_t*)(smem + lr * 272 + cl * 2) = *(uint32_t*)&h0;
                *(uint32_t*)(smem + (lr + 8) * 272 + cl * 2) = *(uint32_t*)&h1;
            }
        }
        __syncthreads();
        __half* gv = g_u + (size_t)m0 * CDIM + wi;
#pragma unroll
        for (int i = 0; i < 16; i++) {
            const int id = tid + i * 256;
            const int t  = id >> 5;
            const int ch = id & 31;
            *(uint2*)(gv + (size_t)t * CDIM + ch * 4) =
                *(uint2*)(smem + t * 272 + ch * 8);
        }
    }
}

// ---------------------------------------------------------------------------
// Window attention: S = Y·x^T (split-bf16 3-pass) + col bias c; softmax fp32;
// O = P·u (fp16) -> out fp32 + Bout.  Writes d_out directly (no K3).
//   smem: S stages [0,64K) (Yh|Yl|xh|xl 8KB planes x2 stages);
//         u stages reuse slot-0 of each stage; P fp16 @65536;
//         Ss fp32 overlays stage0; tok @81920; cw @82176.
// ---------------------------------------------------------------------------
#define ATTN_SMEM 82432
__global__ __launch_bounds__(128) void window_attn(float* __restrict__ out)
{
    extern __shared__ __align__(16) char asm_[];
    const uint32_t sb = smem_u32(asm_);
    int* tok = (int*)(asm_ + 81920);
    float* cw = (float*)(asm_ + 82176);
    float (*Ss)[65] = (float(*)[65])asm_;

    const int gb = blockIdx.x;
    const int b = gb >> 8, win = gb & 255, wy = win >> 4, wx = win & 15;
    const int tid = threadIdx.x;
    if (tid < 64) {
        int py = tid >> 3, px = tid & 7;
        tok[tid] = b * 16384 + (wy * 8 + py) * 128 + (wx * 8 + px);
    }
    __syncthreads();
    if (tid < 64) cw[tid] = g_c[tok[tid]];

    const int wid = tid >> 5, lane = tid & 31;
    const int g = lane >> 2, t4 = lane & 3;
    const int la = lane & 15, lh = lane >> 4;

    uint32_t coff[4];
#pragma unroll
    for (int q = 0; q < 4; q++)
        coff[q] = (uint32_t)((((2 * q + lh) ^ (lane & 7)) & 7) * 16);

    // ---- S-phase loaders: planes 0,1 = Y hi/lo ; planes 2,3 = x hi/lo ----
    const __nv_bfloat16* sQK[16];
    uint32_t dQK[16];
#pragma unroll
    for (int i = 0; i < 16; i++) {
        const int id = tid + i * 128;
        const int p  = id >> 9;
        const int t  = (id >> 3) & 63;
        const int ci = id & 7;
        sQK[i] = (p < 2 ? g_y + (size_t)tok[t] * 768 + p * 384
                        : g_xs + (size_t)tok[t] * 768 + (p - 2) * 384) + ci * 8;
        dQK[i] = sb + (uint32_t)(p * 8192 + t * 128 + ((ci ^ (t & 7)) * 16));
    }

#define PREF_QK(cc) do {                                                      \
        const uint32_t _o = ((cc) & 1) * 32768u;                              \
        _Pragma("unroll")                                                     \
        for (int _i = 0; _i < 16; _i++) {                                     \
            asm volatile("cp.async.cg.shared.global [%0], [%1], 16;"          \
                :: "r"(dQK[_i] + _o), "l"(sQK[_i] + (cc) * 64));              \
        }                                                                     \
        asm volatile("cp.async.commit_group;" ::: "memory");                  \
    } while (0)

    float accS[8][4];
#pragma unroll
    for (int nt = 0; nt < 8; nt++)
#pragma unroll
        for (int i = 0; i < 4; i++) accS[nt][i] = 0.f;

    PREF_QK(0);

#pragma unroll
    for (int cc = 0; cc < 6; cc++) {
        asm volatile("cp.async.wait_group 0;" ::: "memory");
        __syncthreads();
        if (cc < 5) PREF_QK(cc + 1);
        const uint32_t st = (cc & 1) * 32768u;
        const uint32_t aYh = sb + st + (uint32_t)((wid * 16 + la) * 128);
        const uint32_t aYl = aYh + 8192;
        const uint32_t bXh = sb + st + 16384 + (uint32_t)(la * 128);
        const uint32_t bXl = bXh + 8192;
#pragma unroll
        for (int kt = 0; kt < 4; kt++) {
            uint32_t yh[4], yl[4];
            LDSM_X4(yh, aYh + coff[kt]);
            LDSM_X4(yl, aYl + coff[kt]);
#pragma unroll
            for (int ntp = 0; ntp < 4; ntp++) {
                uint32_t xh[4], xl[4];
                LDSM_X4(xh, bXh + ntp * 2048 + coff[kt]);
                LDSM_X4(xl, bXl + ntp * 2048 + coff[kt]);
                mma16816(accS[ntp * 2],     yh, xh[0], xh[2]);
                mma16816(accS[ntp * 2 + 1], yh, xh[1], xh[3]);
                mma16816(accS[ntp * 2],     yl, xh[0], xh[2]);
                mma16816(accS[ntp * 2 + 1], yl, xh[1], xh[3]);
                mma16816(accS[ntp * 2],     yh, xl[0], xl[2]);
                mma16816(accS[ntp * 2 + 1], yh, xl[1], xl[3]);
            }
        }
    }
#undef PREF_QK
    __syncthreads();

    // ---- S -> Ss (fp32, overlays stage0) ----
    {
        const int r0 = wid * 16 + g;
#pragma unroll
        for (int nt = 0; nt < 8; nt++) {
            const int col = nt * 8 + t4 * 2;
            Ss[r0][col]         = accS[nt][0];
            Ss[r0][col + 1]     = accS[nt][1];
            Ss[r0 + 8][col]     = accS[nt][2];
            Ss[r0 + 8][col + 1] = accS[nt][3];
        }
    }
    __syncthreads();

    // ---- softmax (fp32, +col bias) + P -> fp16 plane @65536 ----
    if (tid < 64) {
        float m = -1e30f;
#pragma unroll 8
        for (int j = 0; j < 64; j++) m = fmaxf(m, Ss[tid][j] + cw[j]);
        float s = 0.f;
#pragma unroll 8
        for (int j = 0; j < 64; j++) {
            float e = expf(Ss[tid][j] + cw[j] - m);
            Ss[tid][j] = e;
            s += e;
        }
        float inv = 1.f / s;
#pragma unroll 8
        for (int j = 0; j < 64; j += 2) {
            __half2 p2 = __floats2half2_rn(Ss[tid][j] * inv, Ss[tid][j + 1] * inv);
            const int w = j >> 1;
            const uint32_t off = (uint32_t)(tid * 128 +
                (((w >> 2) ^ (tid & 7)) * 16) + (w & 3) * 4);
            *(uint32_t*)(asm_ + 65536 + off) = *(uint32_t*)&p2;
        }
    }
    __syncthreads();

    // ---- P fragments (fp16, loop-invariant) ----
    uint32_t ph[4][4];
    const uint32_t aPh = sb + 65536 + (uint32_t)((wid * 16 + la) * 128);
#pragma unroll
    for (int kt = 0; kt < 4; kt++)
        LDSM_X4(ph[kt], aPh + coff[kt]);
    const int tr0 = tok[wid * 16 + g];
    const int tr1 = tok[wid * 16 + g + 8];

    // ---- O-phase: u loads ----
    const __half* sV[4];
    uint32_t dV[4];
#pragma unroll
    for (int i = 0; i < 4; i++) {
        const int id = tid + i * 128;
        const int t  = id >> 3;
        const int ci = id & 7;
        sV[i] = g_u + (size_t)tok[t] * CDIM + ci * 8;
        dV[i] = sb + (uint32_t)(t * 128 + ((ci ^ (t & 7)) * 16));
    }

#define PREF_V(co) do {                                                       \
        const uint32_t _o = ((co) & 1) * 32768u;                              \
        _Pragma("unroll")                                                     \
        for (int _i = 0; _i < 4; _i++) {                                      \
            asm volatile("cp.async.cg.shared.global [%0], [%1], 16;"          \
                :: "r"(dV[_i] + _o), "l"(sV[_i] + (co) * 64));                \
        }                                                                     \
        asm volatile("cp.async.commit_group;" ::: "memory");                  \
    } while (0)

    PREF_V(0);

    const uint32_t vbase = sb + (uint32_t)(((((lane >> 3) & 1) * 8) + (lane & 7)) * 128);

#pragma unroll
    for (int co = 0; co < 6; co++) {
        asm volatile("cp.async.wait_group 0;" ::: "memory");
        __syncthreads();
        if (co < 5) PREF_V(co + 1);
        const uint32_t bVh = vbase + (co & 1) * 32768u;

        float accO[8][4];
#pragma unroll
        for (int nt = 0; nt < 8; nt++)
#pragma unroll
            for (int i = 0; i < 4; i++) accO[nt][i] = 0.f;

#pragma unroll
        for (int kt = 0; kt < 4; kt++) {
#pragma unroll
            for (int ntp = 0; ntp < 4; ntp++) {
                uint32_t vh[4];
                LDSM_X4_T(vh, bVh + kt * 2048 + coff[ntp]);
                mma16816h(accO[ntp * 2],     ph[kt], vh[0], vh[1]);
                mma16816h(accO[ntp * 2 + 1], ph[kt], vh[2], vh[3]);
            }
        }
#pragma unroll
        for (int nt = 0; nt < 8; nt++) {
            const int col = co * 64 + nt * 8 + t4 * 2;
            float2 bo = *(const float2*)(g_Bout + col);
            *(float2*)(out + (size_t)tr0 * CDIM + col) =
                make_float2(accO[nt][0] + bo.x, accO[nt][1] + bo.y);
            *(float2*)(out + (size_t)tr1 * CDIM + col) =
                make_float2(accO[nt][2] + bo.x, accO[nt][3] + bo.y);
        }
    }
#undef PREF_V
}

// ---------------------------------------------------------------------------
extern "C" void kernel_launch(void* const* d_in, const int* in_sizes, int n_in,
                              void* d_out, int out_size)
{
    const float* x      = (const float*)d_in[0];
    const float* w_qkv  = (const float*)d_in[1];
    const float* b_qkv  = (const float*)d_in[2];
    const float* w_proj = (const float*)d_in[3];
    const float* b_proj = (const float*)d_in[4];
    float* out = (float*)d_out;

    __half* mcat = nullptr;
    cudaGetSymbolAddress((void**)&mcat, g_Mcat);

    cudaFuncSetAttribute(gemm_fused, cudaFuncAttributeMaxDynamicSharedMemorySize,
                         3 * STAGE_BYTES);
    cudaFuncSetAttribute(window_attn, cudaFuncAttributeMaxDynamicSharedMemorySize,
                         ATTN_SMEM);

    // Bias vectors (w1, Bout)
    bias_vec<<<3, 256>>>(w_qkv, b_qkv, w_proj, b_proj);

    // M1^T = (Wq·Wk^T)^T rows 0..383:  C[m][n] = sum_c W[m][384+c]·W[n][c]
    small_gemm<<<dim3(6, 6), 256>>>(w_qkv + 384, w_qkv, mcat, 0,
                                    NQKV, 1, NQKV, 1);
    // M2^T rows 384..767: C[m][n] = sum_c w_proj[c][m]·W[n][768+c]
    small_gemm<<<dim3(6, 6), 256>>>(w_proj, w_qkv + 768, mcat, 384,
                                    1, CDIM, NQKV, 1);

    // x -> fp16 + split planes + column bias
    cvt_split<<<TOKENS / 32, 256>>>(x);

    // [Y|u] = x · Mcat^T
    gemm_fused<<<dim3(6, TOKENS / 128), 256, 3 * STAGE_BYTES>>>();

    // Attention -> d_out (with Bout)
    window_attn<<<NWIN, 128, ATTN_SMEM>>>(out);
}

// round 15
// speedup vs baseline: 1.3773x; 1.0554x over previous
#include <cuda_runtime.h>
#include <cuda_bf16.h>
#include <cuda_fp16.h>
#include <cstdint>
#include <math.h>

// Problem constants (B=8, H=W=128, C=384, window=8)
#define TOKENS   131072              // 8*128*128
#define CDIM     384
#define NQKV     1152
#define NWIN     2048                // 8 * 16 * 16 windows

// ---------------------------------------------------------------------------
// Scratch (allocation-free rule: __device__ globals)
// ---------------------------------------------------------------------------
__device__ __half        g_Mcat[768 * CDIM];              // [M1^T ; M2^T] fp16
__device__ float         g_w1[CDIM];                      // Wk·b_q
__device__ float         g_Bout[CDIM];                    // b_v·Wp + b_p
__device__ __half        g_xh[(size_t)TOKENS * CDIM];     // x fp16 (GEMM A)
__device__ __nv_bfloat16 g_xs[(size_t)TOKENS * 768];      // x split planes [hi|lo]
__device__ float         g_c [(size_t)TOKENS];            // S column bias
__device__ __nv_bfloat16 g_y [(size_t)TOKENS * 768];      // Y split planes [hi|lo]
__device__ __half        g_u [(size_t)TOKENS * CDIM];     // u = x·M2 fp16

__device__ __forceinline__ uint32_t smem_u32(const void* p) {
    uint32_t a;
    asm("{ .reg .u64 tmp; cvta.to.shared.u64 tmp, %1; cvt.u32.u64 %0, tmp; }"
        : "=r"(a) : "l"(p));
    return a;
}

// Split a float2 into packed bf16x2 hi and lo (residual) parts.
__device__ __forceinline__ void split2(float x, float y, uint32_t& hi, uint32_t& lo) {
    uint32_t h;
    asm("cvt.rn.bf16x2.f32 %0, %1, %2;" : "=r"(h) : "f"(y), "f"(x));
    float h0 = __uint_as_float(h << 16);
    float h1 = __uint_as_float(h & 0xffff0000u);
    float r0 = x - h0, r1 = y - h1;
    asm("cvt.rn.bf16x2.f32 %0, %1, %2;" : "=r"(lo) : "f"(r1), "f"(r0));
    hi = h;
}

// bf16 HMMA (attention S-phase)
__device__ __forceinline__ void mma16816(float* c, const uint32_t* a,
                                         uint32_t b0, uint32_t b1) {
    asm volatile(
        "mma.sync.aligned.m16n8k16.row.col.f32.bf16.bf16.f32 "
        "{%0,%1,%2,%3}, {%4,%5,%6,%7}, {%8,%9}, {%0,%1,%2,%3};\n"
        : "+f"(c[0]), "+f"(c[1]), "+f"(c[2]), "+f"(c[3])
        : "r"(a[0]), "r"(a[1]), "r"(a[2]), "r"(a[3]), "r"(b0), "r"(b1));
}

// fp16 HMMA (GEMM + attention O-phase)
__device__ __forceinline__ void mma16816h(float* c, const uint32_t* a,
                                          uint32_t b0, uint32_t b1) {
    asm volatile(
        "mma.sync.aligned.m16n8k16.row.col.f32.f16.f16.f32 "
        "{%0,%1,%2,%3}, {%4,%5,%6,%7}, {%8,%9}, {%0,%1,%2,%3};\n"
        : "+f"(c[0]), "+f"(c[1]), "+f"(c[2]), "+f"(c[3])
        : "r"(a[0]), "r"(a[1]), "r"(a[2]), "r"(a[3]), "r"(b0), "r"(b1));
}

#define LDSM_X4(r, a) \
    asm volatile("ldmatrix.sync.aligned.m8n8.x4.shared.b16 {%0,%1,%2,%3}, [%4];" \
        : "=r"((r)[0]), "=r"((r)[1]), "=r"((r)[2]), "=r"((r)[3]) : "r"(a))

#define LDSM_X4_T(r, a) \
    asm volatile("ldmatrix.sync.aligned.m8n8.x4.trans.shared.b16 {%0,%1,%2,%3}, [%4];" \
        : "=r"((r)[0]), "=r"((r)[1]), "=r"((r)[2]), "=r"((r)[3]) : "r"(a))

// ---------------------------------------------------------------------------
// Small fp32 GEMM -> fp16: C[m0out+m][n] = sum_c A[m*saR+c*saC]*B[n*sbR+c*sbC]
// ---------------------------------------------------------------------------
__global__ __launch_bounds__(256) void small_gemm(
    const float* __restrict__ A, const float* __restrict__ B,
    __half* __restrict__ Cc, int m0out,
    int saR, int saC, int sbR, int sbC)
{
    __shared__ float As[16][68], Bs[16][68];
    const int tid = threadIdx.x;
    const int tx = tid & 15, ty = tid >> 4;
    const int bm = blockIdx.y * 64, bn = blockIdx.x * 64;
    float acc[4][4];
#pragma unroll
    for (int i = 0; i < 4; i++)
#pragma unroll
        for (int j = 0; j < 4; j++) acc[i][j] = 0.f;

    for (int k0 = 0; k0 < CDIM; k0 += 16) {
#pragma unroll
        for (int i = 0; i < 4; i++) {
            const int id = tid + i * 256;
            const int m = id & 63, k = id >> 6;
            As[k][m] = A[(size_t)(bm + m) * saR + (size_t)(k0 + k) * saC];
            Bs[k][m] = B[(size_t)(bn + m) * sbR + (size_t)(k0 + k) * sbC];
        }
        __syncthreads();
#pragma unroll
        for (int k = 0; k < 16; k++)
#pragma unroll
            for (int i = 0; i < 4; i++)
#pragma unroll
                for (int j = 0; j < 4; j++)
                    acc[i][j] += As[k][ty * 4 + i] * Bs[k][tx * 4 + j];
        __syncthreads();
    }
#pragma unroll
    for (int i = 0; i < 4; i++)
#pragma unroll
        for (int j = 0; j < 4; j++)
            Cc[(size_t)(m0out + bm + ty * 4 + i) * CDIM + bn + tx * 4 + j] =
                __float2half(acc[i][j]);
}

// ---------------------------------------------------------------------------
// Bias vectors: w1[a] = sum_c W[a][384+c]*b_q[c];  Bout[n] = b_v·Wp + b_p
// ---------------------------------------------------------------------------
__global__ __launch_bounds__(256) void bias_vec(
    const float* __restrict__ w_qkv, const float* __restrict__ b_qkv,
    const float* __restrict__ w_proj, const float* __restrict__ b_proj)
{
    const int t = blockIdx.x * 256 + threadIdx.x;
    if (t < CDIM) {
        float s = 0.f;
        for (int c = 0; c < CDIM; c++)
            s += w_qkv[(size_t)t * NQKV + 384 + c] * b_qkv[c];
        g_w1[t] = s;
    } else if (t < 2 * CDIM) {
        const int n = t - CDIM;
        float s = 0.f;
        for (int c = 0; c < CDIM; c++)
            s += b_qkv[768 + c] * w_proj[(size_t)c * CDIM + n];
        g_Bout[n] = s + b_proj[n];
    }
}

// ---------------------------------------------------------------------------
// x -> fp16 (g_xh) + split-bf16 planes (g_xs) + column bias c = x·w1 (g_c)
// ---------------------------------------------------------------------------
__global__ __launch_bounds__(256) void cvt_split(const float* __restrict__ x)
{
    __shared__ float w1s[CDIM];
    for (int i = threadIdx.x; i < CDIM; i += 256) w1s[i] = g_w1[i];
    __syncthreads();

    const int row = blockIdx.x * 32 + (threadIdx.x >> 3);
    const int j   = threadIdx.x & 7;
    const float* xr = x + (size_t)row * CDIM;
    float dot = 0.f;
#pragma unroll
    for (int k = 0; k < 12; k++) {
        const int col = j * 4 + k * 32;
        float4 v = *(const float4*)(xr + col);
        __half2 a = __floats2half2_rn(v.x, v.y);
        __half2 b = __floats2half2_rn(v.z, v.w);
        *(uint2*)(g_xh + (size_t)row * CDIM + col) =
            make_uint2(*(uint32_t*)&a, *(uint32_t*)&b);
        uint32_t h0, l0, h1, l1;
        split2(v.x, v.y, h0, l0);
        split2(v.z, v.w, h1, l1);
        *(uint2*)(g_xs + (size_t)row * 768 + col)       = make_uint2(h0, h1);
        *(uint2*)(g_xs + (size_t)row * 768 + 384 + col) = make_uint2(l0, l1);
        dot += v.x * w1s[col] + v.y * w1s[col + 1]
             + v.z * w1s[col + 2] + v.w * w1s[col + 3];
    }
#pragma unroll
    for (int o = 4; o > 0; o >>= 1) dot += __shfl_down_sync(0xffffffffu, dot, o, 8);
    if (j == 0) g_c[row] = dot;
}

// ---------------------------------------------------------------------------
// Fused GEMM: [Y|u] = x(fp16) @ Mcat^T (r14, validated)
// ---------------------------------------------------------------------------
#define STAGE_BYTES 32768u
__global__ __launch_bounds__(256, 2) void gemm_fused()
{
    extern __shared__ __align__(16) char smem[];
    const uint32_t smemBase = smem_u32(smem);

    const int tid  = threadIdx.x;
    const int wid  = tid >> 5;
    const int lane = tid & 31;
    const int g    = lane >> 2;
    const int t4   = lane & 3;
    const int m0   = blockIdx.y * 128;
    const int n0   = blockIdx.x * 128;
    const int wm   = (wid & 3) * 32;
    const int wn   = (wid >> 2) * 64;

    const __half* srcs[8];
    uint32_t dsts[8];
#pragma unroll
    for (int i = 0; i < 8; i++) {
        const int id = tid + i * 256;
        const int ab = id >> 10;
        const int r  = (id >> 3) & 127;
        const int ch = id & 7;
        if (ab == 0) srcs[i] = g_xh   + (size_t)(m0 + r) * CDIM + ch * 8;
        else         srcs[i] = g_Mcat + (size_t)(n0 + r) * CDIM + ch * 8;
        dsts[i] = smemBase + (uint32_t)(ab * 16384 + r * 128 + ((ch ^ (r & 7)) * 16));
    }

#define PREFETCH(s, off) do {                                                 \
        _Pragma("unroll")                                                     \
        for (int _i = 0; _i < 8; _i++) {                                      \
            asm volatile("cp.async.cg.shared.global [%0], [%1], 16;"          \
                :: "r"(dsts[_i] + (off)), "l"(srcs[_i] + (s) * 64));          \
        }                                                                     \
        asm volatile("cp.async.commit_group;" ::: "memory");                  \
    } while (0)

    const int la = lane & 15;
    const int h  = lane >> 4;
    const int s7 = la & 7;
    uint32_t coff[4];
#pragma unroll
    for (int q = 0; q < 4; q++)
        coff[q] = (uint32_t)((((2 * q + h) ^ s7) & 7) * 16);
    const uint32_t aBase = smemBase + (uint32_t)((wm + la) * 128);
    const uint32_t bBase = smemBase + 16384 + (uint32_t)((wn + la) * 128);

    float acc[2][8][4];
#pragma unroll
    for (int mt = 0; mt < 2; mt++)
#pragma unroll
        for (int nt = 0; nt < 8; nt++)
#pragma unroll
            for (int i = 0; i < 4; i++) acc[mt][nt][i] = 0.f;

    PREFETCH(0, 0);
    PREFETCH(1, STAGE_BYTES);

#pragma unroll
    for (int s = 0; s < 6; s++) {
        asm volatile("cp.async.wait_group 1;" ::: "memory");
        __syncthreads();
        if (s < 4) PREFETCH(s + 2, ((s + 2) % 3) * STAGE_BYTES);
        else asm volatile("cp.async.commit_group;" ::: "memory");
        const uint32_t off = (s % 3) * STAGE_BYTES;

#pragma unroll
        for (int q = 0; q < 4; q++) {
            uint32_t a[2][4];
#pragma unroll
            for (int mt = 0; mt < 2; mt++)
                LDSM_X4(a[mt], aBase + off + mt * 2048 + coff[q]);
#pragma unroll
            for (int ntp = 0; ntp < 4; ntp++) {
                uint32_t b[4];
                LDSM_X4(b, bBase + off + ntp * 2048 + coff[q]);
                mma16816h(acc[0][ntp * 2],     a[0], b[0], b[2]);
                mma16816h(acc[0][ntp * 2 + 1], a[0], b[1], b[3]);
                mma16816h(acc[1][ntp * 2],     a[1], b[0], b[2]);
                mma16816h(acc[1][ntp * 2 + 1], a[1], b[1], b[3]);
            }
        }
    }
#undef PREFETCH

    __syncthreads();
    if (blockIdx.x < 3) {
        const int wi = blockIdx.x * 128;
#pragma unroll
        for (int mt = 0; mt < 2; mt++) {
            const int lr = wm + mt * 16 + g;
#pragma unroll
            for (int nt = 0; nt < 8; nt++) {
                const int cl = wn + (nt >> 1) * 16 + (nt & 1) * 8 + t4 * 2;
                uint32_t hh, ll;
                split2(acc[mt][nt][0], acc[mt][nt][1], hh, ll);
                *(uint32_t*)(smem + lr * 272 + cl * 2) = hh;
                *(uint32_t*)(smem + 34816 + lr * 272 + cl * 2) = ll;
                split2(acc[mt][nt][2], acc[mt][nt][3], hh, ll);
                *(uint32_t*)(smem + (lr + 8) * 272 + cl * 2) = hh;
                *(uint32_t*)(smem + 34816 + (lr + 8) * 272 + cl * 2) = ll;
            }
        }
        __syncthreads();
        __nv_bfloat16* gb = g_y + (size_t)m0 * 768 + wi;
#pragma unroll
        for (int i = 0; i < 16; i++) {
            const int id = tid + i * 256;
            const int t  = id >> 5;
            const int ch = id & 31;
            *(uint2*)(gb + (size_t)t * 768 + ch * 4) =
                *(uint2*)(smem + t * 272 + ch * 8);
            *(uint2*)(gb + (size_t)t * 768 + 384 + ch * 4) =
                *(uint2*)(smem + 34816 + t * 272 + ch * 8);
        }
    } else {
        const int wi = (blockIdx.x - 3) * 128;
#pragma unroll
        for (int mt = 0; mt < 2; mt++) {
            const int lr = wm + mt * 16 + g;
#pragma unroll
            for (int nt = 0; nt < 8; nt++) {
                const int cl = wn + (nt >> 1) * 16 + (nt & 1) * 8 + t4 * 2;
                __half2 h0 = __floats2half2_rn(acc[mt][nt][0], acc[mt][nt][1]);
                __half2 h1 = __floats2half2_rn(acc[mt][nt][2], acc[mt][nt][3]);
                *(uint32_t*)(smem + lr * 272 + cl * 2) = *(uint32_t*)&h0;
                *(uint32_t*)(smem + (lr + 8) * 272 + cl * 2) = *(uint32_t*)&h1;
            }
        }
        __syncthreads();
        __half* gv = g_u + (size_t)m0 * CDIM + wi;
#pragma unroll
        for (int i = 0; i < 16; i++) {
            const int id = tid + i * 256;
            const int t  = id >> 5;
            const int ch = id & 31;
            *(uint2*)(gv + (size_t)t * CDIM + ch * 4) =
                *(uint2*)(smem + t * 272 + ch * 8);
        }
    }
}

// ---------------------------------------------------------------------------
// Window attention v5: 4 blocks/SM (smem diet).
//   S-phase: 32-col chunks, stage = 4 planes x 4KB = 16KB, 2 stages @0/@16384.
//            64B rows, swizzle ci ^ ((t>>1)&3).
//   Ss fp32 overlays stage region after S; P fp16 plane @32768 (128B rows);
//   O-phase: u 64-col chunks (8KB) in the two 16KB stages; tok @40960, cw @41216.
// ---------------------------------------------------------------------------
#define ATTN_SMEM 41472
__global__ __launch_bounds__(128, 4) void window_attn(float* __restrict__ out)
{
    extern __shared__ __align__(16) char asm_[];
    const uint32_t sb = smem_u32(asm_);
    int* tok = (int*)(asm_ + 40960);
    float* cw = (float*)(asm_ + 41216);
    float (*Ss)[65] = (float(*)[65])asm_;

    const int gb = blockIdx.x;
    const int b = gb >> 8, win = gb & 255, wy = win >> 4, wx = win & 15;
    const int tid = threadIdx.x;
    if (tid < 64) {
        int py = tid >> 3, px = tid & 7;
        tok[tid] = b * 16384 + (wy * 8 + py) * 128 + (wx * 8 + px);
    }
    __syncthreads();
    if (tid < 64) cw[tid] = g_c[tok[tid]];

    const int wid = tid >> 5, lane = tid & 31;
    const int g = lane >> 2, t4 = lane & 3;
    const int la = lane & 15, lh = lane >> 4;

    // S-phase coff: 64B rows, 4 chunks, swizzle (la>>1)&3
    uint32_t coffS[2];
#pragma unroll
    for (int q = 0; q < 2; q++)
        coffS[q] = (uint32_t)((((2 * q + lh) ^ ((la >> 1) & 3)) & 3) * 16);
    // O-phase coff: 128B rows, 8 chunks, swizzle la&7 (r13 validated)
    uint32_t coffO[4];
#pragma unroll
    for (int q = 0; q < 4; q++)
        coffO[q] = (uint32_t)((((2 * q + lh) ^ (la & 7)) & 7) * 16);

    // ---- S-phase loaders: 1024 x 16B chunks per stage; 8 per thread ----
    // planes p: 0=Yh 1=Yl 2=xh 3=xl; row t 64B (4 chunks)
    const __nv_bfloat16* sQK[8];
    uint32_t dQK[8];
#pragma unroll
    for (int i = 0; i < 8; i++) {
        const int id = tid + i * 128;          // < 1024
        const int p  = id >> 8;
        const int t  = (id >> 2) & 63;
        const int ci = id & 3;
        sQK[i] = (p < 2 ? g_y + (size_t)tok[t] * 768 + p * 384
                        : g_xs + (size_t)tok[t] * 768 + (p - 2) * 384) + ci * 8;
        dQK[i] = sb + (uint32_t)(p * 4096 + t * 64 + (((ci ^ ((t >> 1) & 3)) & 3) * 16));
    }

#define PREF_QK(cc) do {                                                      \
        const uint32_t _o = ((cc) & 1) * 16384u;                              \
        _Pragma("unroll")                                                     \
        for (int _i = 0; _i < 8; _i++) {                                      \
            asm volatile("cp.async.cg.shared.global [%0], [%1], 16;"          \
                :: "r"(dQK[_i] + _o), "l"(sQK[_i] + (cc) * 32));              \
        }                                                                     \
        asm volatile("cp.async.commit_group;" ::: "memory");                  \
    } while (0)

    float accS[8][4];
#pragma unroll
    for (int nt = 0; nt < 8; nt++)
#pragma unroll
        for (int i = 0; i < 4; i++) accS[nt][i] = 0.f;

    PREF_QK(0);

#pragma unroll
    for (int cc = 0; cc < 12; cc++) {
        asm volatile("cp.async.wait_group 0;" ::: "memory");
        __syncthreads();
        if (cc < 11) PREF_QK(cc + 1);
        const uint32_t st = (cc & 1) * 16384u;
        const uint32_t aYh = sb + st + (uint32_t)((wid * 16 + la) * 64);
        const uint32_t aYl = aYh + 4096;
        const uint32_t bXh = sb + st + 8192 + (uint32_t)(la * 64);
        const uint32_t bXl = bXh + 4096;
#pragma unroll
        for (int kt = 0; kt < 2; kt++) {
            uint32_t yh[4], yl[4];
            LDSM_X4(yh, aYh + coffS[kt]);
            LDSM_X4(yl, aYl + coffS[kt]);
#pragma unroll
            for (int ntp = 0; ntp < 4; ntp++) {
                uint32_t xh[4], xl[4];
                LDSM_X4(xh, bXh + ntp * 1024 + coffS[kt]);
                LDSM_X4(xl, bXl + ntp * 1024 + coffS[kt]);
                mma16816(accS[ntp * 2],     yh, xh[0], xh[2]);
                mma16816(accS[ntp * 2 + 1], yh, xh[1], xh[3]);
                mma16816(accS[ntp * 2],     yl, xh[0], xh[2]);
                mma16816(accS[ntp * 2 + 1], yl, xh[1], xh[3]);
                mma16816(accS[ntp * 2],     yh, xl[0], xl[2]);
                mma16816(accS[ntp * 2 + 1], yh, xl[1], xl[3]);
            }
        }
    }
#undef PREF_QK
    __syncthreads();

    // ---- S -> Ss (fp32, overlays stage region) ----
    {
        const int r0 = wid * 16 + g;
#pragma unroll
        for (int nt = 0; nt < 8; nt++) {
            const int col = nt * 8 + t4 * 2;
            Ss[r0][col]         = accS[nt][0];
            Ss[r0][col + 1]     = accS[nt][1];
            Ss[r0 + 8][col]     = accS[nt][2];
            Ss[r0 + 8][col + 1] = accS[nt][3];
        }
    }
    __syncthreads();

    // ---- softmax (fp32, +col bias) + P -> fp16 plane @32768 ----
    if (tid < 64) {
        float m = -1e30f;
#pragma unroll 8
        for (int j = 0; j < 64; j++) m = fmaxf(m, Ss[tid][j] + cw[j]);
        float s = 0.f;
#pragma unroll 8
        for (int j = 0; j < 64; j++) {
            float e = expf(Ss[tid][j] + cw[j] - m);
            Ss[tid][j] = e;
            s += e;
        }
        float inv = 1.f / s;
#pragma unroll 8
        for (int j = 0; j < 64; j += 2) {
            __half2 p2 = __floats2half2_rn(Ss[tid][j] * inv, Ss[tid][j + 1] * inv);
            const int w = j >> 1;
            const uint32_t off = (uint32_t)(tid * 128 +
                (((w >> 2) ^ (tid & 7)) * 16) + (w & 3) * 4);
            *(uint32_t*)(asm_ + 32768 + off) = *(uint32_t*)&p2;
        }
    }
    __syncthreads();

    // ---- P fragments (fp16, loop-invariant; 128B rows -> coffO) ----
    uint32_t ph[4][4];
    const uint32_t aPh = sb + 32768 + (uint32_t)((wid * 16 + la) * 128);
#pragma unroll
    for (int kt = 0; kt < 4; kt++)
        LDSM_X4(ph[kt], aPh + coffO[kt]);
    const int tr0 = tok[wid * 16 + g];
    const int tr1 = tok[wid * 16 + g + 8];

    // ---- O-phase loaders: u fp16, 64-col chunks (8KB) in 16KB stages ----
    const __half* sV[4];
    uint32_t dV[4];
#pragma unroll
    for (int i = 0; i < 4; i++) {
        const int id = tid + i * 128;          // < 512
        const int t  = id >> 3;
        const int ci = id & 7;
        sV[i] = g_u + (size_t)tok[t] * CDIM + ci * 8;
        dV[i] = sb + (uint32_t)(t * 128 + ((ci ^ (t & 7)) * 16));
    }

#define PREF_V(co) do {                                                       \
        const uint32_t _o = ((co) & 1) * 16384u;                              \
        _Pragma("unroll")                                                     \
        for (int _i = 0; _i < 4; _i++) {                                      \
            asm volatile("cp.async.cg.shared.global [%0], [%1], 16;"          \
                :: "r"(dV[_i] + _o), "l"(sV[_i] + (co) * 64));                \
        }                                                                     \
        asm volatile("cp.async.commit_group;" ::: "memory");                  \
    } while (0)

    PREF_V(0);

    const uint32_t vbase = sb + (uint32_t)(((((lane >> 3) & 1) * 8) + (lane & 7)) * 128);

#pragma unroll
    for (int co = 0; co < 6; co++) {
        asm volatile("cp.async.wait_group 0;" ::: "memory");
        __syncthreads();
        if (co < 5) PREF_V(co + 1);
        const uint32_t bVh = vbase + (co & 1) * 16384u;

        float accO[8][4];
#pragma unroll
        for (int nt = 0; nt < 8; nt++)
#pragma unroll
            for (int i = 0; i < 4; i++) accO[nt][i] = 0.f;

#pragma unroll
        for (int kt = 0; kt < 4; kt++) {
#pragma unroll
            for (int ntp = 0; ntp < 4; ntp++) {
                uint32_t vh[4];
                LDSM_X4_T(vh, bVh + kt * 2048 + coffO[ntp]);
                mma16816h(accO[ntp * 2],     ph[kt], vh[0], vh[1]);
                mma16816h(accO[ntp * 2 + 1], ph[kt], vh[2], vh[3]);
            }
        }
#pragma unroll
        for (int nt = 0; nt < 8; nt++) {
            const int col = co * 64 + nt * 8 + t4 * 2;
            float2 bo = *(const float2*)(g_Bout + col);
            *(float2*)(out + (size_t)tr0 * CDIM + col) =
                make_float2(accO[nt][0] + bo.x, accO[nt][1] + bo.y);
            *(float2*)(out + (size_t)tr1 * CDIM + col) =
                make_float2(accO[nt][2] + bo.x, accO[nt][3] + bo.y);
        }
    }
#undef PREF_V
}

// ---------------------------------------------------------------------------
extern "C" void kernel_launch(void* const* d_in, const int* in_sizes, int n_in,
                              void* d_out, int out_size)
{
    const float* x      = (const float*)d_in[0];
    const float* w_qkv  = (const float*)d_in[1];
    const float* b_qkv  = (const float*)d_in[2];
    const float* w_proj = (const float*)d_in[3];
    const float* b_proj = (const float*)d_in[4];
    float* out = (float*)d_out;

    __half* mcat = nullptr;
    cudaGetSymbolAddress((void**)&mcat, g_Mcat);

    cudaFuncSetAttribute(gemm_fused, cudaFuncAttributeMaxDynamicSharedMemorySize,
                         3 * STAGE_BYTES);
    cudaFuncSetAttribute(window_attn, cudaFuncAttributeMaxDynamicSharedMemorySize,
                         ATTN_SMEM);

    // Bias vectors (w1, Bout)
    bias_vec<<<3, 256>>>(w_qkv, b_qkv, w_proj, b_proj);

    // M1^T rows 0..383:  C[m][n] = sum_c W[m][384+c]·W[n][c]
    small_gemm<<<dim3(6, 6), 256>>>(w_qkv + 384, w_qkv, mcat, 0,
                                    NQKV, 1, NQKV, 1);
    // M2^T rows 384..767: C[m][n] = sum_c w_proj[c][m]·W[n][768+c]
    small_gemm<<<dim3(6, 6), 256>>>(w_proj, w_qkv + 768, mcat, 384,
                                    1, CDIM, NQKV, 1);

    // x -> fp16 + split planes + column bias
    cvt_split<<<TOKENS / 32, 256>>>(x);

    // [Y|u] = x · Mcat^T
    gemm_fused<<<dim3(6, TOKENS / 128), 256, 3 * STAGE_BYTES>>>();

    // Attention -> d_out (with Bout)
    window_attn<<<NWIN, 128, ATTN_SMEM>>>(out);
}